// round 2
// baseline (speedup 1.0000x reference)
#include <cuda_runtime.h>
#include <math.h>
#include <float.h>

// ---------------------------------------------------------------------------
// Problem constants
// ---------------------------------------------------------------------------
constexpr int cB   = 16;
constexpr int cN   = 2048;
constexpr int cG   = 128;
constexpr int cM   = 32;
constexpr int cDM  = 384;
constexpr int cNL  = 12;
constexpr int cDI  = 768;
constexpr int cDS  = 16;
constexpr int cDTR = 24;
constexpr int cTOK = cB * cG;        // 2048 tokens
constexpr int cPTS = cTOK * cM;      // 65536 points

// ---------------------------------------------------------------------------
// Scratch (device globals; no dynamic allocation allowed)
// ---------------------------------------------------------------------------
__device__ __align__(16) float g_center[cTOK * 3];
__device__ __align__(16) float g_nb[cPTS * 3];
__device__ __align__(16) float g_f1[(size_t)cPTS * 128];
__device__ __align__(16) float g_cat[(size_t)cPTS * 512];   // [fg(256) | f2(256)]
__device__ __align__(16) float g_f3[(size_t)cPTS * 512];
__device__ __align__(16) float g_f4[(size_t)cPTS * 384];
__device__ __align__(16) float g_pos1[cTOK * 128];
__device__ __align__(16) float g_h[cTOK * cDM];
__device__ __align__(16) float g_res[cTOK * cDM];
__device__ __align__(16) float g_xln[cTOK * cDM];
__device__ __align__(16) float g_xz[(size_t)cTOK * 2 * cDI];
__device__ __align__(16) float g_xc[(size_t)cTOK * cDI];
__device__ __align__(16) float g_dbl[cTOK * 56];
__device__ __align__(16) float g_dt[(size_t)cTOK * cDI];
__device__ __align__(16) float g_u[(size_t)cTOK * cDI];

// ---------------------------------------------------------------------------
// FPS: per batch, exact replication of reference scan (incl. tie-breaking)
// ---------------------------------------------------------------------------
__global__ void fps_kernel(const float* __restrict__ xyz) {
    int b = blockIdx.x;
    __shared__ float px[cN], py[cN], pz[cN], dmin[cN];
    __shared__ float rv[256];
    __shared__ int   ri[256];
    int tid = threadIdx.x;
    for (int i = tid; i < cN; i += 256) {
        px[i] = xyz[(b * cN + i) * 3 + 0];
        py[i] = xyz[(b * cN + i) * 3 + 1];
        pz[i] = xyz[(b * cN + i) * 3 + 2];
        dmin[i] = 1e10f;
    }
    __syncthreads();
    int cur = 0;
    for (int g = 0; g < cG; g++) {
        float cx = px[cur], cy = py[cur], cz = pz[cur];
        if (tid == 0) {
            g_center[(b * cG + g) * 3 + 0] = cx;
            g_center[(b * cG + g) * 3 + 1] = cy;
            g_center[(b * cG + g) * 3 + 2] = cz;
        }
        float bv = -1.f; int bi = 0x7fffffff;
        for (int i = tid; i < cN; i += 256) {
            float dx = __fsub_rn(px[i], cx);
            float dy = __fsub_rn(py[i], cy);
            float dz = __fsub_rn(pz[i], cz);
            float dd = __fadd_rn(__fadd_rn(__fmul_rn(dx, dx), __fmul_rn(dy, dy)),
                                 __fmul_rn(dz, dz));
            float dm = fminf(dmin[i], dd);
            dmin[i] = dm;
            if (dm > bv) { bv = dm; bi = i; }  // strict > keeps lowest index in-thread
        }
        rv[tid] = bv; ri[tid] = bi;
        __syncthreads();
        for (int s = 128; s > 0; s >>= 1) {
            if (tid < s) {
                float ov = rv[tid + s]; int oi = ri[tid + s];
                if (ov > rv[tid] || (ov == rv[tid] && oi < ri[tid])) {
                    rv[tid] = ov; ri[tid] = oi;
                }
            }
            __syncthreads();
        }
        cur = ri[0];
        __syncthreads();
    }
}

// ---------------------------------------------------------------------------
// KNN: 32 smallest d2, ties -> lowest index (matches lax.top_k); writes nb
// ---------------------------------------------------------------------------
__global__ void knn_kernel(const float* __restrict__ xyz) {
    int bg = blockIdx.x;
    int b = bg >> 7;
    __shared__ float d2s[cN];
    __shared__ float rv[256];
    __shared__ int   ri[256];
    int tid = threadIdx.x;
    float cx = g_center[bg * 3 + 0], cy = g_center[bg * 3 + 1], cz = g_center[bg * 3 + 2];
    const float* P = xyz + (size_t)b * cN * 3;
    for (int i = tid; i < cN; i += 256) {
        float dx = __fsub_rn(cx, P[i * 3 + 0]);
        float dy = __fsub_rn(cy, P[i * 3 + 1]);
        float dz = __fsub_rn(cz, P[i * 3 + 2]);
        d2s[i] = __fadd_rn(__fadd_rn(__fmul_rn(dx, dx), __fmul_rn(dy, dy)),
                           __fmul_rn(dz, dz));
    }
    __syncthreads();
    for (int m = 0; m < cM; m++) {
        float bv = FLT_MAX; int bi = 0x7fffffff;
        for (int i = tid; i < cN; i += 256) {
            float v = d2s[i];
            if (v < bv) { bv = v; bi = i; }
        }
        rv[tid] = bv; ri[tid] = bi;
        __syncthreads();
        for (int s = 128; s > 0; s >>= 1) {
            if (tid < s) {
                float ov = rv[tid + s]; int oi = ri[tid + s];
                if (ov < rv[tid] || (ov == rv[tid] && oi < ri[tid])) {
                    rv[tid] = ov; ri[tid] = oi;
                }
            }
            __syncthreads();
        }
        int idx = ri[0];
        if (tid < 3) {
            float c = (tid == 0) ? cx : ((tid == 1) ? cy : cz);
            g_nb[((size_t)bg * cM + m) * 3 + tid] = __fsub_rn(P[idx * 3 + tid], c);
        }
        if (tid == 0) d2s[idx] = FLT_MAX;
        __syncthreads();
    }
}

// ---------------------------------------------------------------------------
// Encoder stage 1: f1 = relu(bn(x @ e1w1^T + e1b1))
// ---------------------------------------------------------------------------
__global__ void f1_kernel(const float* __restrict__ w1, const float* __restrict__ b1,
                          const float* __restrict__ g1, const float* __restrict__ bb1) {
    int i = blockIdx.x;
    int j = threadIdx.x;
    float x0 = g_nb[i * 3 + 0], x1 = g_nb[i * 3 + 1], x2 = g_nb[i * 3 + 2];
    float v = x0 * w1[j * 3 + 0] + x1 * w1[j * 3 + 1] + x2 * w1[j * 3 + 2] + b1[j];
    v = v * (g1[j] * rsqrtf(1.0f + 1e-5f)) + bb1[j];
    g_f1[(size_t)i * 128 + j] = fmaxf(v, 0.f);
}

// Group max of f2 (cols 256..511 of g_cat), broadcast into cols 0..255
__global__ void fgmax_kernel() {
    int g = blockIdx.x, c = threadIdx.x;
    float mx = -FLT_MAX;
    for (int m = 0; m < cM; m++)
        mx = fmaxf(mx, g_cat[((size_t)g * cM + m) * 512 + 256 + c]);
    for (int m = 0; m < cM; m++)
        g_cat[((size_t)g * cM + m) * 512 + c] = mx;
}

// tokens = max over M of f4 -> g_h
__global__ void tokmax_kernel() {
    int bg = blockIdx.x;
    for (int j = 0; j < 3; j++) {
        int c = threadIdx.x + j * 128;
        float mx = -FLT_MAX;
        for (int m = 0; m < cM; m++)
            mx = fmaxf(mx, g_f4[((size_t)bg * cM + m) * 384 + c]);
        g_h[bg * 384 + c] = mx;
    }
}

// ---------------------------------------------------------------------------
// Positional MLP
// ---------------------------------------------------------------------------
__global__ void pos1_kernel(const float* __restrict__ pw1, const float* __restrict__ pb1) {
    int idx = blockIdx.x * blockDim.x + threadIdx.x;
    if (idx >= cTOK * 128) return;
    int t = idx >> 7, j = idx & 127;
    float x0 = g_center[t * 3 + 0], x1 = g_center[t * 3 + 1], x2 = g_center[t * 3 + 2];
    float v = x0 * pw1[j * 3 + 0] + x1 * pw1[j * 3 + 1] + x2 * pw1[j * 3 + 2] + pb1[j];
    // jax.nn.gelu default (tanh approximation)
    float v3 = v * v * v;
    float g = 0.5f * v * (1.0f + tanhf(0.7978845608028654f * (v + 0.044715f * v3)));
    g_pos1[idx] = g;
}

__global__ void pos2_kernel(const float* __restrict__ pw2, const float* __restrict__ pb2) {
    int idx = blockIdx.x * blockDim.x + threadIdx.x;
    if (idx >= cTOK * 384) return;
    int t = idx / 384, n = idx % 384;
    const float4* a4 = (const float4*)(g_pos1 + t * 128);
    const float4* w4 = (const float4*)(pw2 + n * 128);
    float acc = pb2[n];
#pragma unroll 8
    for (int k = 0; k < 32; k++) {
        float4 a = a4[k], w = w4[k];
        acc += a.x * w.x + a.y * w.y + a.z * w.z + a.w * w.w;
    }
    g_h[idx] += acc;  // g_h holds tokens from tokmax
}

// ---------------------------------------------------------------------------
// Tiled SGEMM: C = epi(A @ W^T). A (M,K) row-major lda, W (N,K) row-major.
// EPI 0: +bias (nullable). EPI 1: relu(bn(dot+bias)).
// All of M%BM, N%BN, K%BK must be 0 (arranged by caller).
// ---------------------------------------------------------------------------
template<int BM, int BN, int BK, int TM, int TN, int EPI>
__global__ void __launch_bounds__((BM / TM) * (BN / TN))
sgemm_k(const float* __restrict__ A, const float* __restrict__ W,
        const float* __restrict__ bias,
        const float* __restrict__ bng, const float* __restrict__ bnb,
        float* __restrict__ C, int K, int lda, int ldc)
{
    constexpr int THREADS = (BM / TM) * (BN / TN);
    constexpr int KV = BK / 4;
    __shared__ float As[BK][BM];
    __shared__ float Ws[BK][BN];
    const int tid = threadIdx.x;
    const int m0 = blockIdx.x * BM;
    const int n0 = blockIdx.y * BN;
    const int tx = tid % (BN / TN);
    const int ty = tid / (BN / TN);

    float acc[TM][TN];
#pragma unroll
    for (int i = 0; i < TM; i++)
#pragma unroll
        for (int j = 0; j < TN; j++) acc[i][j] = 0.f;

    const float* Ap = A + (size_t)m0 * lda;
    const float* Wp = W + (size_t)n0 * K;

    for (int k0 = 0; k0 < K; k0 += BK) {
#pragma unroll
        for (int v = 0; v < (BM * KV) / THREADS; v++) {
            int s = tid + v * THREADS;
            int row = s / KV, kp = (s % KV) * 4;
            float4 q = *(const float4*)(Ap + (size_t)row * lda + k0 + kp);
            As[kp + 0][row] = q.x; As[kp + 1][row] = q.y;
            As[kp + 2][row] = q.z; As[kp + 3][row] = q.w;
        }
#pragma unroll
        for (int v = 0; v < (BN * KV) / THREADS; v++) {
            int s = tid + v * THREADS;
            int row = s / KV, kp = (s % KV) * 4;
            float4 q = *(const float4*)(Wp + (size_t)row * K + k0 + kp);
            Ws[kp + 0][row] = q.x; Ws[kp + 1][row] = q.y;
            Ws[kp + 2][row] = q.z; Ws[kp + 3][row] = q.w;
        }
        __syncthreads();
#pragma unroll
        for (int k = 0; k < BK; k++) {
            float ar[TM], br[TN];
#pragma unroll
            for (int i = 0; i < TM; i += 4) {
                float4 q = *(const float4*)&As[k][ty * TM + i];
                ar[i] = q.x; ar[i + 1] = q.y; ar[i + 2] = q.z; ar[i + 3] = q.w;
            }
#pragma unroll
            for (int j = 0; j < TN; j += 4) {
                float4 q = *(const float4*)&Ws[k][tx * TN + j];
                br[j] = q.x; br[j + 1] = q.y; br[j + 2] = q.z; br[j + 3] = q.w;
            }
#pragma unroll
            for (int i = 0; i < TM; i++)
#pragma unroll
                for (int j = 0; j < TN; j++)
                    acc[i][j] += ar[i] * br[j];
        }
        __syncthreads();
    }

#pragma unroll
    for (int i = 0; i < TM; i++) {
        int m = m0 + ty * TM + i;
#pragma unroll
        for (int j = 0; j < TN; j++) {
            int n = n0 + tx * TN + j;
            float v = acc[i][j];
            if (bias) v += bias[n];
            if (EPI == 1)
                v = fmaxf(v * (bng[n] * rsqrtf(1.0f + 1e-5f)) + bnb[n], 0.f);
            C[(size_t)m * ldc + n] = v;
        }
    }
}

// ---------------------------------------------------------------------------
// Residual accumulate + LayerNorm (block per token, 128 threads, 384 ch)
// ---------------------------------------------------------------------------
__device__ __forceinline__ float block_sum_128(float v, float* sm) {
    int tid = threadIdx.x;
    sm[tid] = v; __syncthreads();
    for (int s = 64; s > 0; s >>= 1) {
        if (tid < s) sm[tid] += sm[tid + s];
        __syncthreads();
    }
    float r = sm[0]; __syncthreads();
    return r;
}

__global__ void resln_kernel(const float* __restrict__ w, const float* __restrict__ b,
                             int first) {
    __shared__ float sm[128];
    int t = blockIdx.x;
    float v[3];
#pragma unroll
    for (int j = 0; j < 3; j++) {
        int c = threadIdx.x + j * 128;
        float r = g_h[t * 384 + c];
        if (!first) r += g_res[t * 384 + c];
        g_res[t * 384 + c] = r;
        v[j] = r;
    }
    float mean = block_sum_128(v[0] + v[1] + v[2], sm) * (1.0f / 384.0f);
    float sq = 0.f;
#pragma unroll
    for (int j = 0; j < 3; j++) { float d = v[j] - mean; sq += d * d; }
    float var = block_sum_128(sq, sm) * (1.0f / 384.0f);
    float inv = rsqrtf(var + 1e-5f);
#pragma unroll
    for (int j = 0; j < 3; j++) {
        int c = threadIdx.x + j * 128;
        g_xln[t * 384 + c] = (v[j] - mean) * inv * w[c] + b[c];
    }
}

__global__ void final_kernel(const float* __restrict__ w, const float* __restrict__ b,
                             float* __restrict__ out) {
    __shared__ float sm[128];
    int t = blockIdx.x;
    float v[3];
#pragma unroll
    for (int j = 0; j < 3; j++) {
        int c = threadIdx.x + j * 128;
        v[j] = g_h[t * 384 + c] + g_res[t * 384 + c];
    }
    float mean = block_sum_128(v[0] + v[1] + v[2], sm) * (1.0f / 384.0f);
    float sq = 0.f;
#pragma unroll
    for (int j = 0; j < 3; j++) { float d = v[j] - mean; sq += d * d; }
    float var = block_sum_128(sq, sm) * (1.0f / 384.0f);
    float inv = rsqrtf(var + 1e-5f);
#pragma unroll
    for (int j = 0; j < 3; j++) {
        int c = threadIdx.x + j * 128;
        out[t * 384 + c] = (v[j] - mean) * inv * w[c] + b[c];
    }
}

// ---------------------------------------------------------------------------
// Depthwise causal conv (DC=4) + bias + silu
// ---------------------------------------------------------------------------
__global__ void conv_kernel(const float* __restrict__ cw, const float* __restrict__ cb) {
    int idx = blockIdx.x * blockDim.x + threadIdx.x;   // t*768 + d
    if (idx >= cTOK * cDI) return;
    int t = idx / cDI, d = idx % cDI;
    int l = t & 127;
    int tbase = t - l;   // start of this batch's token block
    float acc = cb[d];
#pragma unroll
    for (int k = 0; k < 4; k++) {
        int lk = l - 3 + k;
        if (lk >= 0)
            acc += g_xz[(size_t)(tbase + lk) * 1536 + d] * cw[d * 4 + k];
    }
    float sig = 1.0f / (1.0f + expf(-acc));
    g_xc[idx] = acc * sig;
}

// ---------------------------------------------------------------------------
// xp projection: dbl[t, 0..55] = xc[t,:] @ xp_w^T   (xp_w: 56 x 768)
// ---------------------------------------------------------------------------
__global__ void xp_kernel(const float* __restrict__ W) {
    __shared__ __align__(16) float a[768];
    int t = blockIdx.x;
    for (int i = threadIdx.x; i < 768; i += 64) a[i] = g_xc[(size_t)t * 768 + i];
    __syncthreads();
    int n = threadIdx.x;
    if (n < 56) {
        const float4* w4 = (const float4*)(W + (size_t)n * 768);
        const float4* a4 = (const float4*)a;
        float acc = 0.f;
#pragma unroll 4
        for (int k = 0; k < 192; k++) {
            float4 wv = w4[k], av = a4[k];
            acc += av.x * wv.x + av.y * wv.y + av.z * wv.z + av.w * wv.w;
        }
        g_dbl[t * 56 + n] = acc;
    }
}

// ---------------------------------------------------------------------------
// dt = softplus(dbl[:, :24] @ dt_w^T + dt_b)   (dt_w: 768 x 24)
// ---------------------------------------------------------------------------
__global__ void dt_kernel(const float* __restrict__ W, const float* __restrict__ bvec) {
    int idx = blockIdx.x * blockDim.x + threadIdx.x;   // t*768 + d
    if (idx >= cTOK * cDI) return;
    int t = idx / cDI, d = idx % cDI;
    const float* dbl = g_dbl + t * 56;
    const float* w = W + d * 24;
    float acc = bvec[d];
#pragma unroll
    for (int r = 0; r < 24; r++) acc += dbl[r] * w[r];
    // stable softplus = max(x,0) + log1p(exp(-|x|))
    float sp = fmaxf(acc, 0.f) + log1pf(expf(-fabsf(acc)));
    g_dt[idx] = sp;
}

// ---------------------------------------------------------------------------
// Selective scan + D skip + silu(z) gate.
// One thread per (b, d, s); 16 lanes per d reduce via shfl.
// grid (48, 16), block 256.
// ---------------------------------------------------------------------------
__global__ void scan_kernel(const float* __restrict__ Alog, const float* __restrict__ Dp) {
    int b = blockIdx.y;
    int lane16 = threadIdx.x & 15;
    int dl = threadIdx.x >> 4;           // 0..15
    int d = blockIdx.x * 16 + dl;
    float A = -expf(Alog[d * 16 + lane16]);
    float Dpd = Dp[d];
    float h = 0.f;
    for (int l = 0; l < 128; l++) {
        int t = b * 128 + l;
        float dt = g_dt[(size_t)t * cDI + d];
        float xin = g_xc[(size_t)t * cDI + d];
        float Bm = g_dbl[t * 56 + 24 + lane16];
        float Cc = g_dbl[t * 56 + 40 + lane16];
        h = expf(dt * A) * h + dt * xin * Bm;
        float y = h * Cc;
#pragma unroll
        for (int off = 8; off > 0; off >>= 1)
            y += __shfl_xor_sync(0xffffffffu, y, off, 16);
        if (lane16 == 0) {
            y += Dpd * xin;
            float z = g_xz[(size_t)t * 1536 + 768 + d];
            float sz = z / (1.0f + expf(-z));
            g_u[(size_t)t * cDI + d] = y * sz;
        }
    }
}

// ---------------------------------------------------------------------------
// Host-side launch sequence
// ---------------------------------------------------------------------------
extern "C" void kernel_launch(void* const* d_in, const int* in_sizes, int n_in,
                              void* d_out, int out_size) {
    const float* xyz   = (const float*)d_in[0];
    const float* e1w1  = (const float*)d_in[1];
    const float* e1b1  = (const float*)d_in[2];
    const float* bn1g  = (const float*)d_in[3];
    const float* bn1b  = (const float*)d_in[4];
    const float* e1w2  = (const float*)d_in[5];
    const float* e1b2  = (const float*)d_in[6];
    const float* e2w1  = (const float*)d_in[7];
    const float* e2b1  = (const float*)d_in[8];
    const float* bn2g  = (const float*)d_in[9];
    const float* bn2b  = (const float*)d_in[10];
    const float* e2w2  = (const float*)d_in[11];
    const float* e2b2  = (const float*)d_in[12];
    const float* pw1   = (const float*)d_in[13];
    const float* pb1   = (const float*)d_in[14];
    const float* pw2   = (const float*)d_in[15];
    const float* pb2   = (const float*)d_in[16];
    const float* in_w  = (const float*)d_in[17];
    const float* convw = (const float*)d_in[18];
    const float* convb = (const float*)d_in[19];
    const float* xp_w  = (const float*)d_in[20];
    const float* dt_w  = (const float*)d_in[21];
    const float* dt_b  = (const float*)d_in[22];
    const float* A_log = (const float*)d_in[23];
    const float* Dp    = (const float*)d_in[24];
    const float* out_w = (const float*)d_in[25];
    const float* lnw   = (const float*)d_in[26];
    const float* lnb   = (const float*)d_in[27];
    const float* fnw   = (const float*)d_in[28];
    const float* fnb   = (const float*)d_in[29];
    float* out = (float*)d_out;

    float *g_cat_p, *g_f1_p, *g_f3_p, *g_f4_p, *g_xln_p, *g_xz_p, *g_u_p, *g_h_p;
    cudaGetSymbolAddress((void**)&g_cat_p, g_cat);
    cudaGetSymbolAddress((void**)&g_f1_p,  g_f1);
    cudaGetSymbolAddress((void**)&g_f3_p,  g_f3);
    cudaGetSymbolAddress((void**)&g_f4_p,  g_f4);
    cudaGetSymbolAddress((void**)&g_xln_p, g_xln);
    cudaGetSymbolAddress((void**)&g_xz_p,  g_xz);
    cudaGetSymbolAddress((void**)&g_u_p,   g_u);
    cudaGetSymbolAddress((void**)&g_h_p,   g_h);

    // ---- grouping ----
    fps_kernel<<<cB, 256>>>(xyz);
    knn_kernel<<<cTOK, 256>>>(xyz);

    // ---- encoder ----
    f1_kernel<<<cPTS, 128>>>(e1w1, e1b1, bn1g, bn1b);
    // f2: (65536,128)@(256,128)^T + bias -> g_cat cols 256..511
    sgemm_k<128, 128, 16, 8, 8, 0><<<dim3(cPTS / 128, 2), 256>>>(
        g_f1_p, e1w2, e1b2, nullptr, nullptr, g_cat_p + 256, 128, 128, 512);
    fgmax_kernel<<<cTOK, 256>>>();
    // f3: (65536,512)@(512,512)^T -> bn+relu
    sgemm_k<128, 128, 16, 8, 8, 1><<<dim3(cPTS / 128, 4), 256>>>(
        g_cat_p, e2w1, e2b1, bn2g, bn2b, g_f3_p, 512, 512, 512);
    // f4: (65536,512)@(384,512)^T + bias
    sgemm_k<128, 128, 16, 8, 8, 0><<<dim3(cPTS / 128, 3), 256>>>(
        g_f3_p, e2w2, e2b2, nullptr, nullptr, g_f4_p, 512, 512, 384);
    tokmax_kernel<<<cTOK, 128>>>();

    // ---- positional MLP ----
    pos1_kernel<<<(cTOK * 128 + 255) / 256, 256>>>(pw1, pb1);
    pos2_kernel<<<(cTOK * 384 + 255) / 256, 256>>>(pw2, pb2);

    // ---- mamba layers ----
    for (int i = 0; i < cNL; i++) {
        const float* in_w_i  = in_w  + (size_t)i * 2 * cDI * cDM;
        const float* cw_i    = convw + (size_t)i * cDI * 4;
        const float* cb_i    = convb + (size_t)i * cDI;
        const float* xp_i    = xp_w  + (size_t)i * 56 * cDI;
        const float* dtw_i   = dt_w  + (size_t)i * cDI * cDTR;
        const float* dtb_i   = dt_b  + (size_t)i * cDI;
        const float* Al_i    = A_log + (size_t)i * cDI * cDS;
        const float* Dp_i    = Dp    + (size_t)i * cDI;
        const float* ow_i    = out_w + (size_t)i * cDM * cDI;
        const float* lnw_i   = lnw   + (size_t)i * cDM;
        const float* lnb_i   = lnb   + (size_t)i * cDM;

        resln_kernel<<<cTOK, 128>>>(lnw_i, lnb_i, i == 0 ? 1 : 0);
        // in-proj: (2048,384)@(1536,384)^T
        sgemm_k<128, 128, 16, 8, 8, 0><<<dim3(cTOK / 128, 12), 256>>>(
            g_xln_p, in_w_i, nullptr, nullptr, nullptr, g_xz_p, 384, 384, 1536);
        conv_kernel<<<(cTOK * cDI + 255) / 256, 256>>>(cw_i, cb_i);
        xp_kernel<<<cTOK, 64>>>(xp_i);
        dt_kernel<<<(cTOK * cDI + 255) / 256, 256>>>(dtw_i, dtb_i);
        scan_kernel<<<dim3(cDI / 16, cB), 256>>>(Al_i, Dp_i);
        // out-proj: (2048,768)@(384,768)^T  (smaller tiles -> 192 blocks)
        sgemm_k<64, 64, 16, 4, 4, 0><<<dim3(cTOK / 64, 6), 256>>>(
            g_u_p, ow_i, nullptr, nullptr, nullptr, g_h_p, 768, 768, 384);
    }

    // ---- final LN ----
    final_kernel<<<cTOK, 128>>>(fnw, fnb, out);
}

// round 3
// speedup vs baseline: 1.0203x; 1.0203x over previous
#include <cuda_runtime.h>
#include <math.h>
#include <float.h>

// ---------------------------------------------------------------------------
// Problem constants
// ---------------------------------------------------------------------------
constexpr int cB   = 16;
constexpr int cN   = 2048;
constexpr int cG   = 128;
constexpr int cM   = 32;
constexpr int cDM  = 384;
constexpr int cNL  = 12;
constexpr int cDI  = 768;
constexpr int cDS  = 16;
constexpr int cDTR = 24;
constexpr int cTOK = cB * cG;        // 2048 tokens
constexpr int cPTS = cTOK * cM;      // 65536 points

// ---------------------------------------------------------------------------
// Scratch (device globals; no dynamic allocation allowed)
// ---------------------------------------------------------------------------
__device__ __align__(16) float g_center[cTOK * 3];
__device__ __align__(16) float g_nb[cPTS * 3];
__device__ __align__(16) float g_f1[(size_t)cPTS * 128];
__device__ __align__(16) float g_cat[(size_t)cPTS * 512];   // [fg(256) | f2(256)]
__device__ __align__(16) float g_f3[(size_t)cPTS * 512];    // also reused as split-K partials
__device__ __align__(16) float g_f4[(size_t)cPTS * 384];
__device__ __align__(16) float g_pos1[cTOK * 128];
__device__ __align__(16) float g_h[cTOK * cDM];
__device__ __align__(16) float g_res[cTOK * cDM];
__device__ __align__(16) float g_xln[cTOK * cDM];
__device__ __align__(16) float g_xz[(size_t)cTOK * 2 * cDI];
__device__ __align__(16) float g_xc[(size_t)cTOK * cDI];
__device__ __align__(16) float g_dbl[cTOK * 56];
__device__ __align__(16) float g_dt[(size_t)cTOK * cDI];
__device__ __align__(16) float g_u[(size_t)cTOK * cDI];

// ---------------------------------------------------------------------------
// packed fp32x2 helpers (Blackwell FFMA2 path — ptxas never emits this itself)
// ---------------------------------------------------------------------------
using u64 = unsigned long long;

__device__ __forceinline__ u64 pack2(float lo, float hi) {
    u64 r;
    asm("mov.b64 %0, {%1,%2};" : "=l"(r) : "f"(lo), "f"(hi));
    return r;
}
__device__ __forceinline__ void unpack2(u64 v, float& lo, float& hi) {
    asm("mov.b64 {%0,%1}, %2;" : "=f"(lo), "=f"(hi) : "l"(v));
}
__device__ __forceinline__ void fma2(u64& d, u64 a, u64 b) {
    asm("fma.rn.f32x2 %0, %1, %2, %3;" : "=l"(d) : "l"(a), "l"(b), "l"(d));
}

// ---------------------------------------------------------------------------
// FPS: per batch, exact replication of reference scan (incl. tie-breaking)
// ---------------------------------------------------------------------------
__global__ void fps_kernel(const float* __restrict__ xyz) {
    int b = blockIdx.x;
    __shared__ float px[cN], py[cN], pz[cN], dmin[cN];
    __shared__ float rv[256];
    __shared__ int   ri[256];
    int tid = threadIdx.x;
    for (int i = tid; i < cN; i += 256) {
        px[i] = xyz[(b * cN + i) * 3 + 0];
        py[i] = xyz[(b * cN + i) * 3 + 1];
        pz[i] = xyz[(b * cN + i) * 3 + 2];
        dmin[i] = 1e10f;
    }
    __syncthreads();
    int cur = 0;
    for (int g = 0; g < cG; g++) {
        float cx = px[cur], cy = py[cur], cz = pz[cur];
        if (tid == 0) {
            g_center[(b * cG + g) * 3 + 0] = cx;
            g_center[(b * cG + g) * 3 + 1] = cy;
            g_center[(b * cG + g) * 3 + 2] = cz;
        }
        float bv = -1.f; int bi = 0x7fffffff;
        for (int i = tid; i < cN; i += 256) {
            float dx = __fsub_rn(px[i], cx);
            float dy = __fsub_rn(py[i], cy);
            float dz = __fsub_rn(pz[i], cz);
            float dd = __fadd_rn(__fadd_rn(__fmul_rn(dx, dx), __fmul_rn(dy, dy)),
                                 __fmul_rn(dz, dz));
            float dm = fminf(dmin[i], dd);
            dmin[i] = dm;
            if (dm > bv) { bv = dm; bi = i; }
        }
        rv[tid] = bv; ri[tid] = bi;
        __syncthreads();
        for (int s = 128; s > 0; s >>= 1) {
            if (tid < s) {
                float ov = rv[tid + s]; int oi = ri[tid + s];
                if (ov > rv[tid] || (ov == rv[tid] && oi < ri[tid])) {
                    rv[tid] = ov; ri[tid] = oi;
                }
            }
            __syncthreads();
        }
        cur = ri[0];
        __syncthreads();
    }
}

// ---------------------------------------------------------------------------
// KNN: 32 smallest d2, ties -> lowest index (matches lax.top_k); writes nb
// ---------------------------------------------------------------------------
__global__ void knn_kernel(const float* __restrict__ xyz) {
    int bg = blockIdx.x;
    int b = bg >> 7;
    __shared__ float d2s[cN];
    __shared__ float rv[256];
    __shared__ int   ri[256];
    int tid = threadIdx.x;
    float cx = g_center[bg * 3 + 0], cy = g_center[bg * 3 + 1], cz = g_center[bg * 3 + 2];
    const float* P = xyz + (size_t)b * cN * 3;
    for (int i = tid; i < cN; i += 256) {
        float dx = __fsub_rn(cx, P[i * 3 + 0]);
        float dy = __fsub_rn(cy, P[i * 3 + 1]);
        float dz = __fsub_rn(cz, P[i * 3 + 2]);
        d2s[i] = __fadd_rn(__fadd_rn(__fmul_rn(dx, dx), __fmul_rn(dy, dy)),
                           __fmul_rn(dz, dz));
    }
    __syncthreads();
    for (int m = 0; m < cM; m++) {
        float bv = FLT_MAX; int bi = 0x7fffffff;
        for (int i = tid; i < cN; i += 256) {
            float v = d2s[i];
            if (v < bv) { bv = v; bi = i; }
        }
        rv[tid] = bv; ri[tid] = bi;
        __syncthreads();
        for (int s = 128; s > 0; s >>= 1) {
            if (tid < s) {
                float ov = rv[tid + s]; int oi = ri[tid + s];
                if (ov < rv[tid] || (ov == rv[tid] && oi < ri[tid])) {
                    rv[tid] = ov; ri[tid] = oi;
                }
            }
            __syncthreads();
        }
        int idx = ri[0];
        if (tid < 3) {
            float c = (tid == 0) ? cx : ((tid == 1) ? cy : cz);
            g_nb[((size_t)bg * cM + m) * 3 + tid] = __fsub_rn(P[idx * 3 + tid], c);
        }
        if (tid == 0) d2s[idx] = FLT_MAX;
        __syncthreads();
    }
}

// ---------------------------------------------------------------------------
// Encoder stage 1: f1 = relu(bn(x @ e1w1^T + e1b1))
// ---------------------------------------------------------------------------
__global__ void f1_kernel(const float* __restrict__ w1, const float* __restrict__ b1,
                          const float* __restrict__ g1, const float* __restrict__ bb1) {
    int i = blockIdx.x;
    int j = threadIdx.x;
    float x0 = g_nb[i * 3 + 0], x1 = g_nb[i * 3 + 1], x2 = g_nb[i * 3 + 2];
    float v = x0 * w1[j * 3 + 0] + x1 * w1[j * 3 + 1] + x2 * w1[j * 3 + 2] + b1[j];
    v = v * (g1[j] * rsqrtf(1.0f + 1e-5f)) + bb1[j];
    g_f1[(size_t)i * 128 + j] = fmaxf(v, 0.f);
}

// Group max of f2 (cols 256..511 of g_cat), broadcast into cols 0..255
__global__ void fgmax_kernel() {
    int g = blockIdx.x, c = threadIdx.x;
    float mx = -FLT_MAX;
    for (int m = 0; m < cM; m++)
        mx = fmaxf(mx, g_cat[((size_t)g * cM + m) * 512 + 256 + c]);
    for (int m = 0; m < cM; m++)
        g_cat[((size_t)g * cM + m) * 512 + c] = mx;
}

// tokens = max over M of f4 -> g_h
__global__ void tokmax_kernel() {
    int bg = blockIdx.x;
    for (int j = 0; j < 3; j++) {
        int c = threadIdx.x + j * 128;
        float mx = -FLT_MAX;
        for (int m = 0; m < cM; m++)
            mx = fmaxf(mx, g_f4[((size_t)bg * cM + m) * 384 + c]);
        g_h[bg * 384 + c] = mx;
    }
}

// ---------------------------------------------------------------------------
// Positional MLP
// ---------------------------------------------------------------------------
__global__ void pos1_kernel(const float* __restrict__ pw1, const float* __restrict__ pb1) {
    int idx = blockIdx.x * blockDim.x + threadIdx.x;
    if (idx >= cTOK * 128) return;
    int t = idx >> 7, j = idx & 127;
    float x0 = g_center[t * 3 + 0], x1 = g_center[t * 3 + 1], x2 = g_center[t * 3 + 2];
    float v = x0 * pw1[j * 3 + 0] + x1 * pw1[j * 3 + 1] + x2 * pw1[j * 3 + 2] + pb1[j];
    float v3 = v * v * v;
    float g = 0.5f * v * (1.0f + tanhf(0.7978845608028654f * (v + 0.044715f * v3)));
    g_pos1[idx] = g;
}

__global__ void pos2_kernel(const float* __restrict__ pw2, const float* __restrict__ pb2) {
    int idx = blockIdx.x * blockDim.x + threadIdx.x;
    if (idx >= cTOK * 384) return;
    int t = idx / 384, n = idx % 384;
    const float4* a4 = (const float4*)(g_pos1 + t * 128);
    const float4* w4 = (const float4*)(pw2 + n * 128);
    float acc = pb2[n];
#pragma unroll 8
    for (int k = 0; k < 32; k++) {
        float4 a = a4[k], w = w4[k];
        acc += a.x * w.x + a.y * w.y + a.z * w.z + a.w * w.w;
    }
    g_h[idx] += acc;
}

// ---------------------------------------------------------------------------
// Double-buffered fp32x2 SGEMM: C = epi(A @ W^T)
//   A (M,K) row-major lda; W (N,K) row-major ldw; C row-major ldc.
//   K param = per-split chunk length; blockIdx.z selects chunk; C += z*zstride.
//   EPI 0: +bias (nullable). EPI 1: relu(bn(dot+bias)). EPI 2: raw partial.
// Requires: BM%TM==0, BN%TN==0, TM%4==0, TN%2==0, threads==256,
//           K%BK==0, BK%4==0.
// ---------------------------------------------------------------------------
template<int BM, int BN, int BK, int TM, int TN, int EPI>
__global__ void __launch_bounds__(256)
sgemm2_k(const float* __restrict__ A, const float* __restrict__ W,
         const float* __restrict__ bias,
         const float* __restrict__ bng, const float* __restrict__ bnb,
         float* __restrict__ C, int K, int lda, int ldw, int ldc,
         size_t zstride)
{
    constexpr int THREADS = 256;
    constexpr int KQ = BK / 4;                   // float4 slots per row
    constexpr int A4 = (BM * BK) / (THREADS * 4);
    constexpr int W4 = (BN * BK) / (THREADS * 4);
    constexpr int NX = BN / TN;                  // threads along N
    constexpr int TNP = TN / 2;

    __shared__ __align__(16) float As[2][BK][BM + 4];
    __shared__ __align__(16) float Ws[2][BK][BN + 4];

    const int tid = threadIdx.x;
    const int m0 = blockIdx.x * BM;
    const int n0 = blockIdx.y * BN;
    const int kbeg = blockIdx.z * K;
    C += (size_t)blockIdx.z * zstride;

    const int tx = tid % NX;
    const int ty = tid / NX;

    u64 acc[TM][TNP];
#pragma unroll
    for (int i = 0; i < TM; i++)
#pragma unroll
        for (int j = 0; j < TNP; j++) acc[i][j] = 0ull;

    float4 ra[A4], rw[W4];

    auto loadG = [&](int k0) {
#pragma unroll
        for (int v = 0; v < A4; v++) {
            int s = tid + v * THREADS;
            int row = s / KQ, kq = (s % KQ) * 4;
            ra[v] = *(const float4*)(A + (size_t)(m0 + row) * lda + kbeg + k0 + kq);
        }
#pragma unroll
        for (int v = 0; v < W4; v++) {
            int s = tid + v * THREADS;
            int row = s / KQ, kq = (s % KQ) * 4;
            rw[v] = *(const float4*)(W + (size_t)(n0 + row) * ldw + kbeg + k0 + kq);
        }
    };
    auto stsG = [&](int buf) {
#pragma unroll
        for (int v = 0; v < A4; v++) {
            int s = tid + v * THREADS;
            int row = s / KQ, kq = (s % KQ) * 4;
            As[buf][kq + 0][row] = ra[v].x;
            As[buf][kq + 1][row] = ra[v].y;
            As[buf][kq + 2][row] = ra[v].z;
            As[buf][kq + 3][row] = ra[v].w;
        }
#pragma unroll
        for (int v = 0; v < W4; v++) {
            int s = tid + v * THREADS;
            int row = s / KQ, kq = (s % KQ) * 4;
            Ws[buf][kq + 0][row] = rw[v].x;
            Ws[buf][kq + 1][row] = rw[v].y;
            Ws[buf][kq + 2][row] = rw[v].z;
            Ws[buf][kq + 3][row] = rw[v].w;
        }
    };

    const int nIter = K / BK;
    loadG(0);
    stsG(0);
    __syncthreads();
    int buf = 0;

    for (int it = 0; it < nIter; it++) {
        bool more = (it + 1 < nIter);
        if (more) loadG((it + 1) * BK);
#pragma unroll
        for (int k = 0; k < BK; k++) {
            float ar[TM];
#pragma unroll
            for (int i = 0; i < TM; i += 4) {
                float4 q = *(const float4*)&As[buf][k][ty * TM + i];
                ar[i] = q.x; ar[i + 1] = q.y; ar[i + 2] = q.z; ar[i + 3] = q.w;
            }
            u64 b2[TNP];
            const u64* wp = (const u64*)&Ws[buf][k][tx * TN];
#pragma unroll
            for (int j = 0; j < TNP; j++) b2[j] = wp[j];
#pragma unroll
            for (int i = 0; i < TM; i++) {
                u64 a2 = pack2(ar[i], ar[i]);
#pragma unroll
                for (int j = 0; j < TNP; j++) fma2(acc[i][j], a2, b2[j]);
            }
        }
        if (more) {
            stsG(buf ^ 1);
            __syncthreads();
            buf ^= 1;
        }
    }

#pragma unroll
    for (int i = 0; i < TM; i++) {
        int m = m0 + ty * TM + i;
#pragma unroll
        for (int j = 0; j < TNP; j++) {
            int n = n0 + tx * TN + 2 * j;
            float lo, hi;
            unpack2(acc[i][j], lo, hi);
            if (EPI != 2 && bias) { lo += bias[n]; hi += bias[n + 1]; }
            if (EPI == 1) {
                lo = fmaxf(lo * (bng[n] * rsqrtf(1.0f + 1e-5f)) + bnb[n], 0.f);
                hi = fmaxf(hi * (bng[n + 1] * rsqrtf(1.0f + 1e-5f)) + bnb[n + 1], 0.f);
            }
            float2 o; o.x = lo; o.y = hi;
            *(float2*)&C[(size_t)m * ldc + n] = o;
        }
    }
}

// Sum split-K partials (fixed order -> deterministic)
__global__ void reduceK_kernel(const float* __restrict__ part, float* __restrict__ dst,
                               int total, int chunks, size_t zstride) {
    int idx = blockIdx.x * blockDim.x + threadIdx.x;
    if (idx >= total) return;
    float s = 0.f;
    for (int c = 0; c < chunks; c++) s += part[idx + (size_t)c * zstride];
    dst[idx] = s;
}

// ---------------------------------------------------------------------------
// Residual accumulate + LayerNorm (block per token, 128 threads, 384 ch)
// ---------------------------------------------------------------------------
__device__ __forceinline__ float block_sum_128(float v, float* sm) {
    int tid = threadIdx.x;
    sm[tid] = v; __syncthreads();
    for (int s = 64; s > 0; s >>= 1) {
        if (tid < s) sm[tid] += sm[tid + s];
        __syncthreads();
    }
    float r = sm[0]; __syncthreads();
    return r;
}

__global__ void resln_kernel(const float* __restrict__ w, const float* __restrict__ b,
                             int first) {
    __shared__ float sm[128];
    int t = blockIdx.x;
    float v[3];
#pragma unroll
    for (int j = 0; j < 3; j++) {
        int c = threadIdx.x + j * 128;
        float r = g_h[t * 384 + c];
        if (!first) r += g_res[t * 384 + c];
        g_res[t * 384 + c] = r;
        v[j] = r;
    }
    float mean = block_sum_128(v[0] + v[1] + v[2], sm) * (1.0f / 384.0f);
    float sq = 0.f;
#pragma unroll
    for (int j = 0; j < 3; j++) { float d = v[j] - mean; sq += d * d; }
    float var = block_sum_128(sq, sm) * (1.0f / 384.0f);
    float inv = rsqrtf(var + 1e-5f);
#pragma unroll
    for (int j = 0; j < 3; j++) {
        int c = threadIdx.x + j * 128;
        g_xln[t * 384 + c] = (v[j] - mean) * inv * w[c] + b[c];
    }
}

__global__ void final_kernel(const float* __restrict__ w, const float* __restrict__ b,
                             float* __restrict__ out) {
    __shared__ float sm[128];
    int t = blockIdx.x;
    float v[3];
#pragma unroll
    for (int j = 0; j < 3; j++) {
        int c = threadIdx.x + j * 128;
        v[j] = g_h[t * 384 + c] + g_res[t * 384 + c];
    }
    float mean = block_sum_128(v[0] + v[1] + v[2], sm) * (1.0f / 384.0f);
    float sq = 0.f;
#pragma unroll
    for (int j = 0; j < 3; j++) { float d = v[j] - mean; sq += d * d; }
    float var = block_sum_128(sq, sm) * (1.0f / 384.0f);
    float inv = rsqrtf(var + 1e-5f);
#pragma unroll
    for (int j = 0; j < 3; j++) {
        int c = threadIdx.x + j * 128;
        out[t * 384 + c] = (v[j] - mean) * inv * w[c] + b[c];
    }
}

// ---------------------------------------------------------------------------
// Depthwise causal conv (DC=4) + bias + silu
// ---------------------------------------------------------------------------
__global__ void conv_kernel(const float* __restrict__ cw, const float* __restrict__ cb) {
    int idx = blockIdx.x * blockDim.x + threadIdx.x;
    if (idx >= cTOK * cDI) return;
    int t = idx / cDI, d = idx % cDI;
    int l = t & 127;
    int tbase = t - l;
    float acc = cb[d];
#pragma unroll
    for (int k = 0; k < 4; k++) {
        int lk = l - 3 + k;
        if (lk >= 0)
            acc += g_xz[(size_t)(tbase + lk) * 1536 + d] * cw[d * 4 + k];
    }
    float sig = 1.0f / (1.0f + expf(-acc));
    g_xc[idx] = acc * sig;
}

// ---------------------------------------------------------------------------
// xp projection: dbl[t, 0..55] = xc[t,:] @ xp_w^T   (xp_w: 56 x 768)
// ---------------------------------------------------------------------------
__global__ void xp_kernel(const float* __restrict__ W) {
    __shared__ __align__(16) float a[768];
    int t = blockIdx.x;
    for (int i = threadIdx.x; i < 768; i += 64) a[i] = g_xc[(size_t)t * 768 + i];
    __syncthreads();
    int n = threadIdx.x;
    if (n < 56) {
        const float4* w4 = (const float4*)(W + (size_t)n * 768);
        const float4* a4 = (const float4*)a;
        float acc = 0.f;
#pragma unroll 4
        for (int k = 0; k < 192; k++) {
            float4 wv = w4[k], av = a4[k];
            acc += av.x * wv.x + av.y * wv.y + av.z * wv.z + av.w * wv.w;
        }
        g_dbl[t * 56 + n] = acc;
    }
}

// ---------------------------------------------------------------------------
// dt = softplus(dbl[:, :24] @ dt_w^T + dt_b)
// ---------------------------------------------------------------------------
__global__ void dt_kernel(const float* __restrict__ W, const float* __restrict__ bvec) {
    int idx = blockIdx.x * blockDim.x + threadIdx.x;
    if (idx >= cTOK * cDI) return;
    int t = idx / cDI, d = idx % cDI;
    const float* dbl = g_dbl + t * 56;
    const float* w = W + d * 24;
    float acc = bvec[d];
#pragma unroll
    for (int r = 0; r < 24; r++) acc += dbl[r] * w[r];
    float sp = fmaxf(acc, 0.f) + log1pf(expf(-fabsf(acc)));
    g_dt[idx] = sp;
}

// ---------------------------------------------------------------------------
// Selective scan + D skip + silu(z) gate.
// ---------------------------------------------------------------------------
__global__ void scan_kernel(const float* __restrict__ Alog, const float* __restrict__ Dp) {
    int b = blockIdx.y;
    int lane16 = threadIdx.x & 15;
    int dl = threadIdx.x >> 4;
    int d = blockIdx.x * 16 + dl;
    float A = -expf(Alog[d * 16 + lane16]);
    float Dpd = Dp[d];
    float h = 0.f;
    for (int l = 0; l < 128; l++) {
        int t = b * 128 + l;
        float dt = g_dt[(size_t)t * cDI + d];
        float xin = g_xc[(size_t)t * cDI + d];
        float Bm = g_dbl[t * 56 + 24 + lane16];
        float Cc = g_dbl[t * 56 + 40 + lane16];
        h = expf(dt * A) * h + dt * xin * Bm;
        float y = h * Cc;
#pragma unroll
        for (int off = 8; off > 0; off >>= 1)
            y += __shfl_xor_sync(0xffffffffu, y, off, 16);
        if (lane16 == 0) {
            y += Dpd * xin;
            float z = g_xz[(size_t)t * 1536 + 768 + d];
            float sz = z / (1.0f + expf(-z));
            g_u[(size_t)t * cDI + d] = y * sz;
        }
    }
}

// ---------------------------------------------------------------------------
// Host-side launch sequence
// ---------------------------------------------------------------------------
extern "C" void kernel_launch(void* const* d_in, const int* in_sizes, int n_in,
                              void* d_out, int out_size) {
    const float* xyz   = (const float*)d_in[0];
    const float* e1w1  = (const float*)d_in[1];
    const float* e1b1  = (const float*)d_in[2];
    const float* bn1g  = (const float*)d_in[3];
    const float* bn1b  = (const float*)d_in[4];
    const float* e1w2  = (const float*)d_in[5];
    const float* e1b2  = (const float*)d_in[6];
    const float* e2w1  = (const float*)d_in[7];
    const float* e2b1  = (const float*)d_in[8];
    const float* bn2g  = (const float*)d_in[9];
    const float* bn2b  = (const float*)d_in[10];
    const float* e2w2  = (const float*)d_in[11];
    const float* e2b2  = (const float*)d_in[12];
    const float* pw1   = (const float*)d_in[13];
    const float* pb1   = (const float*)d_in[14];
    const float* pw2   = (const float*)d_in[15];
    const float* pb2   = (const float*)d_in[16];
    const float* in_w  = (const float*)d_in[17];
    const float* convw = (const float*)d_in[18];
    const float* convb = (const float*)d_in[19];
    const float* xp_w  = (const float*)d_in[20];
    const float* dt_w  = (const float*)d_in[21];
    const float* dt_b  = (const float*)d_in[22];
    const float* A_log = (const float*)d_in[23];
    const float* Dp    = (const float*)d_in[24];
    const float* out_w = (const float*)d_in[25];
    const float* lnw   = (const float*)d_in[26];
    const float* lnb   = (const float*)d_in[27];
    const float* fnw   = (const float*)d_in[28];
    const float* fnb   = (const float*)d_in[29];
    float* out = (float*)d_out;

    float *g_cat_p, *g_f1_p, *g_f3_p, *g_f4_p, *g_xln_p, *g_xz_p, *g_u_p, *g_h_p;
    cudaGetSymbolAddress((void**)&g_cat_p, g_cat);
    cudaGetSymbolAddress((void**)&g_f1_p,  g_f1);
    cudaGetSymbolAddress((void**)&g_f3_p,  g_f3);
    cudaGetSymbolAddress((void**)&g_f4_p,  g_f4);
    cudaGetSymbolAddress((void**)&g_xln_p, g_xln);
    cudaGetSymbolAddress((void**)&g_xz_p,  g_xz);
    cudaGetSymbolAddress((void**)&g_u_p,   g_u);
    cudaGetSymbolAddress((void**)&g_h_p,   g_h);

    // ---- grouping ----
    fps_kernel<<<cB, 256>>>(xyz);
    knn_kernel<<<cTOK, 256>>>(xyz);

    // ---- encoder ----
    f1_kernel<<<cPTS, 128>>>(e1w1, e1b1, bn1g, bn1b);
    // f2: (65536,128)@(256,128)^T + bias -> g_cat cols 256..511
    sgemm2_k<128, 128, 16, 8, 8, 0><<<dim3(cPTS / 128, 2, 1), 256>>>(
        g_f1_p, e1w2, e1b2, nullptr, nullptr, g_cat_p + 256, 128, 128, 128, 512, 0);
    fgmax_kernel<<<cTOK, 256>>>();
    // f3: (65536,512)@(512,512)^T -> bn+relu
    sgemm2_k<128, 128, 16, 8, 8, 1><<<dim3(cPTS / 128, 4, 1), 256>>>(
        g_cat_p, e2w1, e2b1, bn2g, bn2b, g_f3_p, 512, 512, 512, 512, 0);
    // f4: (65536,512)@(384,512)^T + bias
    sgemm2_k<128, 128, 16, 8, 8, 0><<<dim3(cPTS / 128, 3, 1), 256>>>(
        g_f3_p, e2w2, e2b2, nullptr, nullptr, g_f4_p, 512, 512, 512, 384, 0);
    tokmax_kernel<<<cTOK, 128>>>();

    // ---- positional MLP ----
    pos1_kernel<<<(cTOK * 128 + 255) / 256, 256>>>(pw1, pb1);
    pos2_kernel<<<(cTOK * 384 + 255) / 256, 256>>>(pw2, pb2);

    // ---- mamba layers ----
    constexpr int OSPLIT = 4;
    constexpr int OCHUNK = cDI / OSPLIT;          // 192
    const size_t ozstride = (size_t)cTOK * cDM;   // 786432
    for (int i = 0; i < cNL; i++) {
        const float* in_w_i  = in_w  + (size_t)i * 2 * cDI * cDM;
        const float* cw_i    = convw + (size_t)i * cDI * 4;
        const float* cb_i    = convb + (size_t)i * cDI;
        const float* xp_i    = xp_w  + (size_t)i * 56 * cDI;
        const float* dtw_i   = dt_w  + (size_t)i * cDI * cDTR;
        const float* dtb_i   = dt_b  + (size_t)i * cDI;
        const float* Al_i    = A_log + (size_t)i * cDI * cDS;
        const float* Dp_i    = Dp    + (size_t)i * cDI;
        const float* ow_i    = out_w + (size_t)i * cDM * cDI;
        const float* lnw_i   = lnw   + (size_t)i * cDM;
        const float* lnb_i   = lnb   + (size_t)i * cDM;

        resln_kernel<<<cTOK, 128>>>(lnw_i, lnb_i, i == 0 ? 1 : 0);
        // in-proj: (2048,384)@(1536,384)^T — 64x128 tiles, 384 blocks
        sgemm2_k<64, 128, 16, 4, 8, 0><<<dim3(cTOK / 64, 12, 1), 256>>>(
            g_xln_p, in_w_i, nullptr, nullptr, nullptr, g_xz_p, 384, 384, 384, 1536, 0);
        conv_kernel<<<(cTOK * cDI + 255) / 256, 256>>>(cw_i, cb_i);
        xp_kernel<<<cTOK, 64>>>(xp_i);
        dt_kernel<<<(cTOK * cDI + 255) / 256, 256>>>(dtw_i, dtb_i);
        scan_kernel<<<dim3(cDI / 16, cB), 256>>>(Al_i, Dp_i);
        // out-proj: (2048,768)@(384,768)^T — split-K=4 partials into g_f3 scratch
        sgemm2_k<64, 128, 16, 4, 8, 2><<<dim3(cTOK / 64, 3, OSPLIT), 256>>>(
            g_u_p, ow_i, nullptr, nullptr, nullptr, g_f3_p, OCHUNK, 768, 768, 384,
            ozstride);
        reduceK_kernel<<<(cTOK * cDM + 255) / 256, 256>>>(
            g_f3_p, g_h_p, cTOK * cDM, OSPLIT, ozstride);
    }

    // ---- final LN ----
    final_kernel<<<cTOK, 128>>>(fnw, fnb, out);
}

// round 5
// speedup vs baseline: 1.4307x; 1.4022x over previous
#include <cuda_runtime.h>
#include <math.h>
#include <float.h>

// ---------------------------------------------------------------------------
// Problem constants
// ---------------------------------------------------------------------------
constexpr int cB   = 16;
constexpr int cN   = 2048;
constexpr int cG   = 128;
constexpr int cM   = 32;
constexpr int cDM  = 384;
constexpr int cNL  = 12;
constexpr int cDI  = 768;
constexpr int cDS  = 16;
constexpr int cDTR = 24;
constexpr int cTOK = cB * cG;        // 2048 tokens
constexpr int cPTS = cTOK * cM;      // 65536 points

// ---------------------------------------------------------------------------
// Scratch (device globals; no dynamic allocation allowed)
// ---------------------------------------------------------------------------
__device__ __align__(16) float g_center[cTOK * 3];
__device__ __align__(16) float g_nb[cPTS * 3];
__device__ __align__(16) float g_f1[(size_t)cPTS * 128];
__device__ __align__(16) float g_cat[(size_t)cPTS * 512];   // [fg(256) | f2(256)]
__device__ __align__(16) float g_f3[(size_t)cPTS * 512];
__device__ __align__(16) float g_f4[(size_t)cPTS * 384];
__device__ __align__(16) float g_pos1[cTOK * 128];
__device__ __align__(16) float g_h[cTOK * cDM];
__device__ __align__(16) float g_res[cTOK * cDM];
__device__ __align__(16) float g_xln[cTOK * cDM];
__device__ __align__(16) float g_xz[(size_t)cTOK * 2 * cDI];
__device__ __align__(16) float g_xc[(size_t)cTOK * cDI];
__device__ __align__(16) float g_dbl[cTOK * 56];
__device__ __align__(16) float g_dt[(size_t)cTOK * cDI];
__device__ __align__(16) float g_u[(size_t)cTOK * cDI];

using u32 = unsigned int;

__device__ __forceinline__ u32 cvt_tf32(float x) {
    u32 r;
    asm("cvt.rna.tf32.f32 %0, %1;" : "=r"(r) : "f"(x));
    return r;
}

__device__ __forceinline__ void mma_tf32(float* c, u32 a0, u32 a1, u32 a2, u32 a3,
                                         u32 b0, u32 b1) {
    asm volatile(
        "mma.sync.aligned.m16n8k8.row.col.f32.tf32.tf32.f32 "
        "{%0,%1,%2,%3}, {%4,%5,%6,%7}, {%8,%9}, {%0,%1,%2,%3};"
        : "+f"(c[0]), "+f"(c[1]), "+f"(c[2]), "+f"(c[3])
        : "r"(a0), "r"(a1), "r"(a2), "r"(a3), "r"(b0), "r"(b1));
}

// ---------------------------------------------------------------------------
// Tensor-core tf32 GEMM: C[M,N] = epi(A[M,K] @ W[N,K]^T)
//   128x128 CTA tile, 8 warps (4 along M x 2 along N), warp tile 32x64.
//   BK=16, double-buffered smem, [k][m] layout with +8 pad (conflict-free).
//   Requires M%128==0, N%128==0, K%16==0.
//   EPI 0: +bias (nullable). EPI 1: relu(bn(.+bias)).
// ---------------------------------------------------------------------------
template<int EPI>
__global__ void __launch_bounds__(256)
tcmma_gemm(const float* __restrict__ A, const float* __restrict__ W,
           const float* __restrict__ bias, const float* __restrict__ bng,
           const float* __restrict__ bnb, float* __restrict__ C,
           int K, int lda, int ldw, int ldc)
{
    constexpr int PAD = 8;
    constexpr int LDS_ = 128 + PAD;       // 136
    __shared__ float As[2][16][LDS_];
    __shared__ float Ws[2][16][LDS_];

    const int tid = threadIdx.x;
    const int wid = tid >> 5;
    const int lane = tid & 31;
    const int grp = lane >> 2;            // 0..7
    const int tig = lane & 3;             // 0..3
    const int wm = wid & 3;               // warp M index (0..3)
    const int wn = wid >> 2;              // warp N index (0..1)
    const int m0 = blockIdx.x * 128;
    const int n0 = blockIdx.y * 128;

    float acc[2][8][4];
#pragma unroll
    for (int mt = 0; mt < 2; mt++)
#pragma unroll
        for (int nt = 0; nt < 8; nt++)
#pragma unroll
            for (int r = 0; r < 4; r++) acc[mt][nt][r] = 0.f;

    float4 ra[2], rw[2];
    auto loadG = [&](int kc) {
#pragma unroll
        for (int v = 0; v < 2; v++) {
            int s = tid + v * 256;
            int row = s >> 2;
            int kq = (s & 3) << 2;
            ra[v] = *(const float4*)(A + (size_t)(m0 + row) * lda + kc + kq);
            rw[v] = *(const float4*)(W + (size_t)(n0 + row) * ldw + kc + kq);
        }
    };
    auto stsG = [&](int buf) {
#pragma unroll
        for (int v = 0; v < 2; v++) {
            int s = tid + v * 256;
            int row = s >> 2;
            int kq = (s & 3) << 2;
            As[buf][kq + 0][row] = __uint_as_float(cvt_tf32(ra[v].x));
            As[buf][kq + 1][row] = __uint_as_float(cvt_tf32(ra[v].y));
            As[buf][kq + 2][row] = __uint_as_float(cvt_tf32(ra[v].z));
            As[buf][kq + 3][row] = __uint_as_float(cvt_tf32(ra[v].w));
            Ws[buf][kq + 0][row] = __uint_as_float(cvt_tf32(rw[v].x));
            Ws[buf][kq + 1][row] = __uint_as_float(cvt_tf32(rw[v].y));
            Ws[buf][kq + 2][row] = __uint_as_float(cvt_tf32(rw[v].z));
            Ws[buf][kq + 3][row] = __uint_as_float(cvt_tf32(rw[v].w));
        }
    };

    const int nIter = K >> 4;
    loadG(0);
    stsG(0);
    __syncthreads();
    int buf = 0;

    for (int it = 0; it < nIter; it++) {
        bool more = (it + 1 < nIter);
        if (more) loadG((it + 1) << 4);
#pragma unroll
        for (int ks = 0; ks < 2; ks++) {
            const int k0 = ks * 8;
            u32 af[2][4];
#pragma unroll
            for (int mt = 0; mt < 2; mt++) {
                int m = wm * 32 + mt * 16 + grp;
                af[mt][0] = __float_as_uint(As[buf][k0 + tig][m]);
                af[mt][1] = __float_as_uint(As[buf][k0 + tig][m + 8]);
                af[mt][2] = __float_as_uint(As[buf][k0 + tig + 4][m]);
                af[mt][3] = __float_as_uint(As[buf][k0 + tig + 4][m + 8]);
            }
            u32 bf[8][2];
#pragma unroll
            for (int nt = 0; nt < 8; nt++) {
                int n = wn * 64 + nt * 8 + grp;
                bf[nt][0] = __float_as_uint(Ws[buf][k0 + tig][n]);
                bf[nt][1] = __float_as_uint(Ws[buf][k0 + tig + 4][n]);
            }
#pragma unroll
            for (int mt = 0; mt < 2; mt++)
#pragma unroll
                for (int nt = 0; nt < 8; nt++)
                    mma_tf32(acc[mt][nt], af[mt][0], af[mt][1], af[mt][2], af[mt][3],
                             bf[nt][0], bf[nt][1]);
        }
        if (more) {
            stsG(buf ^ 1);
            __syncthreads();
            buf ^= 1;
        }
    }

    // epilogue
    const float bnscale = rsqrtf(1.0f + 1e-5f);
#pragma unroll
    for (int mt = 0; mt < 2; mt++) {
        int mrow = m0 + wm * 32 + mt * 16 + grp;
#pragma unroll
        for (int nt = 0; nt < 8; nt++) {
            int n = n0 + wn * 64 + nt * 8 + tig * 2;
            float2 lo, hi;
            lo.x = acc[mt][nt][0]; lo.y = acc[mt][nt][1];
            hi.x = acc[mt][nt][2]; hi.y = acc[mt][nt][3];
            if (EPI == 0) {
                if (bias) {
                    lo.x += bias[n]; lo.y += bias[n + 1];
                    hi.x += bias[n]; hi.y += bias[n + 1];
                }
            } else {
                lo.x = fmaxf((lo.x + bias[n]) * (bng[n] * bnscale) + bnb[n], 0.f);
                lo.y = fmaxf((lo.y + bias[n + 1]) * (bng[n + 1] * bnscale) + bnb[n + 1], 0.f);
                hi.x = fmaxf((hi.x + bias[n]) * (bng[n] * bnscale) + bnb[n], 0.f);
                hi.y = fmaxf((hi.y + bias[n + 1]) * (bng[n + 1] * bnscale) + bnb[n + 1], 0.f);
            }
            *(float2*)&C[(size_t)mrow * ldc + n] = lo;
            *(float2*)&C[(size_t)(mrow + 8) * ldc + n] = hi;
        }
    }
}

// ---------------------------------------------------------------------------
// FPS: per batch, exact replication of reference scan (incl. tie-breaking)
// ---------------------------------------------------------------------------
__global__ void fps_kernel(const float* __restrict__ xyz) {
    int b = blockIdx.x;
    __shared__ float px[cN], py[cN], pz[cN], dmin[cN];
    __shared__ float rv[256];
    __shared__ int   ri[256];
    int tid = threadIdx.x;
    for (int i = tid; i < cN; i += 256) {
        px[i] = xyz[(b * cN + i) * 3 + 0];
        py[i] = xyz[(b * cN + i) * 3 + 1];
        pz[i] = xyz[(b * cN + i) * 3 + 2];
        dmin[i] = 1e10f;
    }
    __syncthreads();
    int cur = 0;
    for (int g = 0; g < cG; g++) {
        float cx = px[cur], cy = py[cur], cz = pz[cur];
        if (tid == 0) {
            g_center[(b * cG + g) * 3 + 0] = cx;
            g_center[(b * cG + g) * 3 + 1] = cy;
            g_center[(b * cG + g) * 3 + 2] = cz;
        }
        float bv = -1.f; int bi = 0x7fffffff;
        for (int i = tid; i < cN; i += 256) {
            float dx = __fsub_rn(px[i], cx);
            float dy = __fsub_rn(py[i], cy);
            float dz = __fsub_rn(pz[i], cz);
            float dd = __fadd_rn(__fadd_rn(__fmul_rn(dx, dx), __fmul_rn(dy, dy)),
                                 __fmul_rn(dz, dz));
            float dm = fminf(dmin[i], dd);
            dmin[i] = dm;
            if (dm > bv) { bv = dm; bi = i; }
        }
        rv[tid] = bv; ri[tid] = bi;
        __syncthreads();
        for (int s = 128; s > 0; s >>= 1) {
            if (tid < s) {
                float ov = rv[tid + s]; int oi = ri[tid + s];
                if (ov > rv[tid] || (ov == rv[tid] && oi < ri[tid])) {
                    rv[tid] = ov; ri[tid] = oi;
                }
            }
            __syncthreads();
        }
        cur = ri[0];
        __syncthreads();
    }
}

// ---------------------------------------------------------------------------
// KNN: 32 smallest d2, ties -> lowest index (matches lax.top_k); writes nb
// ---------------------------------------------------------------------------
__global__ void knn_kernel(const float* __restrict__ xyz) {
    int bg = blockIdx.x;
    int b = bg >> 7;
    __shared__ float d2s[cN];
    __shared__ float rv[256];
    __shared__ int   ri[256];
    int tid = threadIdx.x;
    float cx = g_center[bg * 3 + 0], cy = g_center[bg * 3 + 1], cz = g_center[bg * 3 + 2];
    const float* P = xyz + (size_t)b * cN * 3;
    for (int i = tid; i < cN; i += 256) {
        float dx = __fsub_rn(cx, P[i * 3 + 0]);
        float dy = __fsub_rn(cy, P[i * 3 + 1]);
        float dz = __fsub_rn(cz, P[i * 3 + 2]);
        d2s[i] = __fadd_rn(__fadd_rn(__fmul_rn(dx, dx), __fmul_rn(dy, dy)),
                           __fmul_rn(dz, dz));
    }
    __syncthreads();
    for (int m = 0; m < cM; m++) {
        float bv = FLT_MAX; int bi = 0x7fffffff;
        for (int i = tid; i < cN; i += 256) {
            float v = d2s[i];
            if (v < bv) { bv = v; bi = i; }
        }
        rv[tid] = bv; ri[tid] = bi;
        __syncthreads();
        for (int s = 128; s > 0; s >>= 1) {
            if (tid < s) {
                float ov = rv[tid + s]; int oi = ri[tid + s];
                if (ov < rv[tid] || (ov == rv[tid] && oi < ri[tid])) {
                    rv[tid] = ov; ri[tid] = oi;
                }
            }
            __syncthreads();
        }
        int idx = ri[0];
        if (tid < 3) {
            float c = (tid == 0) ? cx : ((tid == 1) ? cy : cz);
            g_nb[((size_t)bg * cM + m) * 3 + tid] = __fsub_rn(P[idx * 3 + tid], c);
        }
        if (tid == 0) d2s[idx] = FLT_MAX;
        __syncthreads();
    }
}

// ---------------------------------------------------------------------------
// Encoder stage 1: f1 = relu(bn(x @ e1w1^T + e1b1))
// ---------------------------------------------------------------------------
__global__ void f1_kernel(const float* __restrict__ w1, const float* __restrict__ b1,
                          const float* __restrict__ g1, const float* __restrict__ bb1) {
    int i = blockIdx.x;
    int j = threadIdx.x;
    float x0 = g_nb[i * 3 + 0], x1 = g_nb[i * 3 + 1], x2 = g_nb[i * 3 + 2];
    float v = x0 * w1[j * 3 + 0] + x1 * w1[j * 3 + 1] + x2 * w1[j * 3 + 2] + b1[j];
    v = v * (g1[j] * rsqrtf(1.0f + 1e-5f)) + bb1[j];
    g_f1[(size_t)i * 128 + j] = fmaxf(v, 0.f);
}

// Group max of f2 (cols 256..511 of g_cat), broadcast into cols 0..255
__global__ void fgmax_kernel() {
    int g = blockIdx.x, c = threadIdx.x;
    float mx = -FLT_MAX;
    for (int m = 0; m < cM; m++)
        mx = fmaxf(mx, g_cat[((size_t)g * cM + m) * 512 + 256 + c]);
    for (int m = 0; m < cM; m++)
        g_cat[((size_t)g * cM + m) * 512 + c] = mx;
}

// tokens = max over M of f4 -> g_h
__global__ void tokmax_kernel() {
    int bg = blockIdx.x;
    for (int j = 0; j < 3; j++) {
        int c = threadIdx.x + j * 128;
        float mx = -FLT_MAX;
        for (int m = 0; m < cM; m++)
            mx = fmaxf(mx, g_f4[((size_t)bg * cM + m) * 384 + c]);
        g_h[bg * 384 + c] = mx;
    }
}

// ---------------------------------------------------------------------------
// Positional MLP
// ---------------------------------------------------------------------------
__global__ void pos1_kernel(const float* __restrict__ pw1, const float* __restrict__ pb1) {
    int idx = blockIdx.x * blockDim.x + threadIdx.x;
    if (idx >= cTOK * 128) return;
    int t = idx >> 7, j = idx & 127;
    float x0 = g_center[t * 3 + 0], x1 = g_center[t * 3 + 1], x2 = g_center[t * 3 + 2];
    float v = x0 * pw1[j * 3 + 0] + x1 * pw1[j * 3 + 1] + x2 * pw1[j * 3 + 2] + pb1[j];
    float v3 = v * v * v;
    float g = 0.5f * v * (1.0f + tanhf(0.7978845608028654f * (v + 0.044715f * v3)));
    g_pos1[idx] = g;
}

__global__ void pos2_kernel(const float* __restrict__ pw2, const float* __restrict__ pb2) {
    int idx = blockIdx.x * blockDim.x + threadIdx.x;
    if (idx >= cTOK * 384) return;
    int t = idx / 384, n = idx % 384;
    const float4* a4 = (const float4*)(g_pos1 + t * 128);
    const float4* w4 = (const float4*)(pw2 + n * 128);
    float acc = pb2[n];
#pragma unroll 8
    for (int k = 0; k < 32; k++) {
        float4 a = a4[k], w = w4[k];
        acc += a.x * w.x + a.y * w.y + a.z * w.z + a.w * w.w;
    }
    g_h[idx] += acc;
}

// ---------------------------------------------------------------------------
// Residual accumulate + LayerNorm (block per token, 128 threads, 384 ch)
// ---------------------------------------------------------------------------
__device__ __forceinline__ float block_sum_128(float v, float* sm) {
    int tid = threadIdx.x;
    sm[tid] = v; __syncthreads();
    for (int s = 64; s > 0; s >>= 1) {
        if (tid < s) sm[tid] += sm[tid + s];
        __syncthreads();
    }
    float r = sm[0]; __syncthreads();
    return r;
}

__global__ void resln_kernel(const float* __restrict__ w, const float* __restrict__ b,
                             int first) {
    __shared__ float sm[128];
    int t = blockIdx.x;
    float v[3];
#pragma unroll
    for (int j = 0; j < 3; j++) {
        int c = threadIdx.x + j * 128;
        float r = g_h[t * 384 + c];
        if (!first) r += g_res[t * 384 + c];
        g_res[t * 384 + c] = r;
        v[j] = r;
    }
    float mean = block_sum_128(v[0] + v[1] + v[2], sm) * (1.0f / 384.0f);
    float sq = 0.f;
#pragma unroll
    for (int j = 0; j < 3; j++) { float d = v[j] - mean; sq += d * d; }
    float var = block_sum_128(sq, sm) * (1.0f / 384.0f);
    float inv = rsqrtf(var + 1e-5f);
#pragma unroll
    for (int j = 0; j < 3; j++) {
        int c = threadIdx.x + j * 128;
        g_xln[t * 384 + c] = (v[j] - mean) * inv * w[c] + b[c];
    }
}

__global__ void final_kernel(const float* __restrict__ w, const float* __restrict__ b,
                             float* __restrict__ out) {
    __shared__ float sm[128];
    int t = blockIdx.x;
    float v[3];
#pragma unroll
    for (int j = 0; j < 3; j++) {
        int c = threadIdx.x + j * 128;
        v[j] = g_h[t * 384 + c] + g_res[t * 384 + c];
    }
    float mean = block_sum_128(v[0] + v[1] + v[2], sm) * (1.0f / 384.0f);
    float sq = 0.f;
#pragma unroll
    for (int j = 0; j < 3; j++) { float d = v[j] - mean; sq += d * d; }
    float var = block_sum_128(sq, sm) * (1.0f / 384.0f);
    float inv = rsqrtf(var + 1e-5f);
#pragma unroll
    for (int j = 0; j < 3; j++) {
        int c = threadIdx.x + j * 128;
        out[t * 384 + c] = (v[j] - mean) * inv * w[c] + b[c];
    }
}

// ---------------------------------------------------------------------------
// Depthwise causal conv (DC=4) + bias + silu
// ---------------------------------------------------------------------------
__global__ void conv_kernel(const float* __restrict__ cw, const float* __restrict__ cb) {
    int idx = blockIdx.x * blockDim.x + threadIdx.x;
    if (idx >= cTOK * cDI) return;
    int t = idx / cDI, d = idx % cDI;
    int l = t & 127;
    int tbase = t - l;
    float acc = cb[d];
#pragma unroll
    for (int k = 0; k < 4; k++) {
        int lk = l - 3 + k;
        if (lk >= 0)
            acc += g_xz[(size_t)(tbase + lk) * 1536 + d] * cw[d * 4 + k];
    }
    float sig = 1.0f / (1.0f + expf(-acc));
    g_xc[idx] = acc * sig;
}

// ---------------------------------------------------------------------------
// xp projection: dbl[t, 0..55] = xc[t,:] @ xp_w^T   (xp_w: 56 x 768)
// ---------------------------------------------------------------------------
__global__ void xp_kernel(const float* __restrict__ W) {
    __shared__ __align__(16) float a[768];
    int t = blockIdx.x;
    for (int i = threadIdx.x; i < 768; i += 64) a[i] = g_xc[(size_t)t * 768 + i];
    __syncthreads();
    int n = threadIdx.x;
    if (n < 56) {
        const float4* w4 = (const float4*)(W + (size_t)n * 768);
        const float4* a4 = (const float4*)a;
        float acc = 0.f;
#pragma unroll 4
        for (int k = 0; k < 192; k++) {
            float4 wv = w4[k], av = a4[k];
            acc += av.x * wv.x + av.y * wv.y + av.z * wv.z + av.w * wv.w;
        }
        g_dbl[t * 56 + n] = acc;
    }
}

// ---------------------------------------------------------------------------
// dt = softplus(dbl[:, :24] @ dt_w^T + dt_b)
// ---------------------------------------------------------------------------
__global__ void dt_kernel(const float* __restrict__ W, const float* __restrict__ bvec) {
    int idx = blockIdx.x * blockDim.x + threadIdx.x;
    if (idx >= cTOK * cDI) return;
    int t = idx / cDI, d = idx % cDI;
    const float* dbl = g_dbl + t * 56;
    const float* w = W + d * 24;
    float acc = bvec[d];
#pragma unroll
    for (int r = 0; r < 24; r++) acc += dbl[r] * w[r];
    float sp = fmaxf(acc, 0.f) + log1pf(expf(-fabsf(acc)));
    g_dt[idx] = sp;
}

// ---------------------------------------------------------------------------
// Selective scan + D skip + silu(z) gate.
// ---------------------------------------------------------------------------
__global__ void scan_kernel(const float* __restrict__ Alog, const float* __restrict__ Dp) {
    int b = blockIdx.y;
    int lane16 = threadIdx.x & 15;
    int dl = threadIdx.x >> 4;
    int d = blockIdx.x * 16 + dl;
    float A = -expf(Alog[d * 16 + lane16]);
    float Dpd = Dp[d];
    float h = 0.f;
    for (int l = 0; l < 128; l++) {
        int t = b * 128 + l;
        float dt = g_dt[(size_t)t * cDI + d];
        float xin = g_xc[(size_t)t * cDI + d];
        float Bm = g_dbl[t * 56 + 24 + lane16];
        float Cc = g_dbl[t * 56 + 40 + lane16];
        h = expf(dt * A) * h + dt * xin * Bm;
        float y = h * Cc;
#pragma unroll
        for (int off = 8; off > 0; off >>= 1)
            y += __shfl_xor_sync(0xffffffffu, y, off, 16);
        if (lane16 == 0) {
            y += Dpd * xin;
            float z = g_xz[(size_t)t * 1536 + 768 + d];
            float sz = z / (1.0f + expf(-z));
            g_u[(size_t)t * cDI + d] = y * sz;
        }
    }
}

// ---------------------------------------------------------------------------
// Host-side launch sequence
// ---------------------------------------------------------------------------
extern "C" void kernel_launch(void* const* d_in, const int* in_sizes, int n_in,
                              void* d_out, int out_size) {
    const float* xyz   = (const float*)d_in[0];
    const float* e1w1  = (const float*)d_in[1];
    const float* e1b1  = (const float*)d_in[2];
    const float* bn1g  = (const float*)d_in[3];
    const float* bn1b  = (const float*)d_in[4];
    const float* e1w2  = (const float*)d_in[5];
    const float* e1b2  = (const float*)d_in[6];
    const float* e2w1  = (const float*)d_in[7];
    const float* e2b1  = (const float*)d_in[8];
    const float* bn2g  = (const float*)d_in[9];
    const float* bn2b  = (const float*)d_in[10];
    const float* e2w2  = (const float*)d_in[11];
    const float* e2b2  = (const float*)d_in[12];
    const float* pw1   = (const float*)d_in[13];
    const float* pb1   = (const float*)d_in[14];
    const float* pw2   = (const float*)d_in[15];
    const float* pb2   = (const float*)d_in[16];
    const float* in_w  = (const float*)d_in[17];
    const float* convw = (const float*)d_in[18];
    const float* convb = (const float*)d_in[19];
    const float* xp_w  = (const float*)d_in[20];
    const float* dt_w  = (const float*)d_in[21];
    const float* dt_b  = (const float*)d_in[22];
    const float* A_log = (const float*)d_in[23];
    const float* Dp    = (const float*)d_in[24];
    const float* out_w = (const float*)d_in[25];
    const float* lnw   = (const float*)d_in[26];
    const float* lnb   = (const float*)d_in[27];
    const float* fnw   = (const float*)d_in[28];
    const float* fnb   = (const float*)d_in[29];
    float* out = (float*)d_out;

    float *g_cat_p, *g_f1_p, *g_f3_p, *g_f4_p, *g_xln_p, *g_xz_p, *g_u_p, *g_h_p;
    cudaGetSymbolAddress((void**)&g_cat_p, g_cat);
    cudaGetSymbolAddress((void**)&g_f1_p,  g_f1);
    cudaGetSymbolAddress((void**)&g_f3_p,  g_f3);
    cudaGetSymbolAddress((void**)&g_f4_p,  g_f4);
    cudaGetSymbolAddress((void**)&g_xln_p, g_xln);
    cudaGetSymbolAddress((void**)&g_xz_p,  g_xz);
    cudaGetSymbolAddress((void**)&g_u_p,   g_u);
    cudaGetSymbolAddress((void**)&g_h_p,   g_h);

    // ---- grouping ----
    fps_kernel<<<cB, 256>>>(xyz);
    knn_kernel<<<cTOK, 256>>>(xyz);

    // ---- encoder ----
    f1_kernel<<<cPTS, 128>>>(e1w1, e1b1, bn1g, bn1b);
    // f2: (65536,128)@(256,128)^T + bias -> g_cat cols 256..511
    tcmma_gemm<0><<<dim3(cPTS / 128, 2), 256>>>(
        g_f1_p, e1w2, e1b2, nullptr, nullptr, g_cat_p + 256, 128, 128, 128, 512);
    fgmax_kernel<<<cTOK, 256>>>();
    // f3: (65536,512)@(512,512)^T -> bn+relu
    tcmma_gemm<1><<<dim3(cPTS / 128, 4), 256>>>(
        g_cat_p, e2w1, e2b1, bn2g, bn2b, g_f3_p, 512, 512, 512, 512);
    // f4: (65536,512)@(384,512)^T + bias
    tcmma_gemm<0><<<dim3(cPTS / 128, 3), 256>>>(
        g_f3_p, e2w2, e2b2, nullptr, nullptr, g_f4_p, 512, 512, 512, 384);
    tokmax_kernel<<<cTOK, 128>>>();

    // ---- positional MLP ----
    pos1_kernel<<<(cTOK * 128 + 255) / 256, 256>>>(pw1, pb1);
    pos2_kernel<<<(cTOK * 384 + 255) / 256, 256>>>(pw2, pb2);

    // ---- mamba layers ----
    for (int i = 0; i < cNL; i++) {
        const float* in_w_i  = in_w  + (size_t)i * 2 * cDI * cDM;
        const float* cw_i    = convw + (size_t)i * cDI * 4;
        const float* cb_i    = convb + (size_t)i * cDI;
        const float* xp_i    = xp_w  + (size_t)i * 56 * cDI;
        const float* dtw_i   = dt_w  + (size_t)i * cDI * cDTR;
        const float* dtb_i   = dt_b  + (size_t)i * cDI;
        const float* Al_i    = A_log + (size_t)i * cDI * cDS;
        const float* Dp_i    = Dp    + (size_t)i * cDI;
        const float* ow_i    = out_w + (size_t)i * cDM * cDI;
        const float* lnw_i   = lnw   + (size_t)i * cDM;
        const float* lnb_i   = lnb   + (size_t)i * cDM;

        resln_kernel<<<cTOK, 128>>>(lnw_i, lnb_i, i == 0 ? 1 : 0);
        // in-proj: (2048,384)@(1536,384)^T
        tcmma_gemm<0><<<dim3(cTOK / 128, 12), 256>>>(
            g_xln_p, in_w_i, nullptr, nullptr, nullptr, g_xz_p, 384, 384, 384, 1536);
        conv_kernel<<<(cTOK * cDI + 255) / 256, 256>>>(cw_i, cb_i);
        xp_kernel<<<cTOK, 64>>>(xp_i);
        dt_kernel<<<(cTOK * cDI + 255) / 256, 256>>>(dtw_i, dtb_i);
        scan_kernel<<<dim3(cDI / 16, cB), 256>>>(Al_i, Dp_i);
        // out-proj: (2048,768)@(384,768)^T
        tcmma_gemm<0><<<dim3(cTOK / 128, 3), 256>>>(
            g_u_p, ow_i, nullptr, nullptr, nullptr, g_h_p, 768, 768, 768, 384);
    }

    // ---- final LN ----
    final_kernel<<<cTOK, 128>>>(fnw, fnb, out);
}

// round 6
// speedup vs baseline: 1.8440x; 1.2889x over previous
#include <cuda_runtime.h>
#include <math.h>
#include <float.h>

// ---------------------------------------------------------------------------
// Problem constants
// ---------------------------------------------------------------------------
constexpr int cB   = 16;
constexpr int cN   = 2048;
constexpr int cG   = 128;
constexpr int cM   = 32;
constexpr int cDM  = 384;
constexpr int cNL  = 12;
constexpr int cDI  = 768;
constexpr int cDS  = 16;
constexpr int cDTR = 24;
constexpr int cTOK = cB * cG;        // 2048 tokens
constexpr int cPTS = cTOK * cM;      // 65536 points

// ---------------------------------------------------------------------------
// Scratch (device globals; no dynamic allocation allowed)
// ---------------------------------------------------------------------------
__device__ __align__(16) float g_center[cTOK * 3];
__device__ __align__(16) float g_nb[cPTS * 3];
__device__ __align__(16) float g_f1[(size_t)cPTS * 128];
__device__ __align__(16) float g_f2[(size_t)cPTS * 256];
__device__ __align__(16) float g_fg[cTOK * 256];
__device__ __align__(16) float g_f3[(size_t)cPTS * 512];
__device__ __align__(16) float g_f4[(size_t)cPTS * 384];
__device__ __align__(16) float g_pos1[cTOK * 128];
__device__ __align__(16) float g_h[cTOK * cDM];
__device__ __align__(16) float g_res[cTOK * cDM];
__device__ __align__(16) float g_xln[cTOK * cDM];
__device__ __align__(16) float g_xz[(size_t)cTOK * 2 * cDI];
__device__ __align__(16) float g_xc[(size_t)cTOK * cDI];
__device__ __align__(16) float g_dbl64[cTOK * 64];
__device__ __align__(16) float g_dt[(size_t)cTOK * cDI];
__device__ __align__(16) float g_u[(size_t)cTOK * cDI];
__device__ __align__(16) float g_xpw[cNL * 64 * cDI];
__device__ __align__(16) float g_dtw[cNL * cDI * 32];

using u32 = unsigned int;

__device__ __forceinline__ u32 cvt_tf32(float x) {
    u32 r;
    asm("cvt.rna.tf32.f32 %0, %1;" : "=r"(r) : "f"(x));
    return r;
}

__device__ __forceinline__ void mma_tf32(float* c, u32 a0, u32 a1, u32 a2, u32 a3,
                                         u32 b0, u32 b1) {
    asm volatile(
        "mma.sync.aligned.m16n8k8.row.col.f32.tf32.tf32.f32 "
        "{%0,%1,%2,%3}, {%4,%5,%6,%7}, {%8,%9}, {%0,%1,%2,%3};"
        : "+f"(c[0]), "+f"(c[1]), "+f"(c[2]), "+f"(c[3])
        : "r"(a0), "r"(a1), "r"(a2), "r"(a3), "r"(b0), "r"(b1));
}

// ---------------------------------------------------------------------------
// Generic tf32 tensor-core GEMM: C = epi(A @ W^T)
//   CTA tile BM x BN, warp grid WGM x WGN, warp tile (BM/WGM) x (BN/WGN).
//   BK=16, double-buffered smem [k][row+8pad] (conflict-free).
//   Requires M%BM==0, N%BN==0, K%16==0.
//   EPI 0: +bias(opt). 1: relu(bn(.+bias)) p1=gamma p2=beta.
//   2: softplus(.+bias). 3: C += . + bias.
//   MODEA 1: A columns [0,256) come from fg[row>>5][k] (group features).
// ---------------------------------------------------------------------------
template<int BM, int BN, int WGM, int WGN, int EPI, int MODEA>
__global__ void __launch_bounds__(WGM * WGN * 32)
tc2(const float* __restrict__ A, const float* __restrict__ W,
    const float* __restrict__ bias, const float* __restrict__ p1,
    const float* __restrict__ p2, float* __restrict__ C,
    int K, int lda, int ldw, int ldc, const float* __restrict__ fg)
{
    constexpr int THREADS = WGM * WGN * 32;
    constexpr int WTM = BM / WGM, WTN = BN / WGN;
    constexpr int MT = WTM / 16, NT = WTN / 8;
    constexpr int LA = BM + 8, LB = BN + 8;
    constexpr int A4 = (BM * 16) / (THREADS * 4);
    constexpr int W4 = (BN * 16) / (THREADS * 4);

    __shared__ float As[2][16][LA];
    __shared__ float Ws[2][16][LB];

    const int tid = threadIdx.x;
    const int wid = tid >> 5, lane = tid & 31;
    const int grp = lane >> 2, tig = lane & 3;
    const int wm = wid % WGM, wn = wid / WGM;
    const int m0 = blockIdx.x * BM, n0 = blockIdx.y * BN;

    float acc[MT][NT][4];
#pragma unroll
    for (int mt = 0; mt < MT; mt++)
#pragma unroll
        for (int nt = 0; nt < NT; nt++)
#pragma unroll
            for (int r = 0; r < 4; r++) acc[mt][nt][r] = 0.f;

    float4 ra[A4], rw[W4];

    auto loadG = [&](int kc) {
#pragma unroll
        for (int v = 0; v < A4; v++) {
            int s = tid + v * THREADS;
            int row = s >> 2, k4 = s & 3;
            int k = kc + k4 * 4;
            const float* src;
            if (MODEA == 1) {
                int r = m0 + row;
                src = (k < 256) ? (fg + ((size_t)(r >> 5)) * 256 + k)
                                : (A + (size_t)r * lda + (k - 256));
            } else {
                src = A + (size_t)(m0 + row) * lda + k;
            }
            ra[v] = *(const float4*)src;
        }
#pragma unroll
        for (int v = 0; v < W4; v++) {
            int s = tid + v * THREADS;
            int row = s >> 2, k4 = s & 3;
            rw[v] = *(const float4*)(W + (size_t)(n0 + row) * ldw + kc + k4 * 4);
        }
    };
    auto stsG = [&](int buf) {
#pragma unroll
        for (int v = 0; v < A4; v++) {
            int s = tid + v * THREADS;
            int row = s >> 2, kq = (s & 3) << 2;
            As[buf][kq + 0][row] = __uint_as_float(cvt_tf32(ra[v].x));
            As[buf][kq + 1][row] = __uint_as_float(cvt_tf32(ra[v].y));
            As[buf][kq + 2][row] = __uint_as_float(cvt_tf32(ra[v].z));
            As[buf][kq + 3][row] = __uint_as_float(cvt_tf32(ra[v].w));
        }
#pragma unroll
        for (int v = 0; v < W4; v++) {
            int s = tid + v * THREADS;
            int row = s >> 2, kq = (s & 3) << 2;
            Ws[buf][kq + 0][row] = __uint_as_float(cvt_tf32(rw[v].x));
            Ws[buf][kq + 1][row] = __uint_as_float(cvt_tf32(rw[v].y));
            Ws[buf][kq + 2][row] = __uint_as_float(cvt_tf32(rw[v].z));
            Ws[buf][kq + 3][row] = __uint_as_float(cvt_tf32(rw[v].w));
        }
    };

    const int nIter = K >> 4;
    loadG(0);
    stsG(0);
    __syncthreads();
    int buf = 0;

    for (int it = 0; it < nIter; it++) {
        bool more = (it + 1 < nIter);
        if (more) loadG((it + 1) << 4);
#pragma unroll
        for (int ks = 0; ks < 2; ks++) {
            const int k0 = ks * 8;
            u32 af[MT][4];
#pragma unroll
            for (int mt = 0; mt < MT; mt++) {
                int m = wm * WTM + mt * 16 + grp;
                af[mt][0] = __float_as_uint(As[buf][k0 + tig][m]);
                af[mt][1] = __float_as_uint(As[buf][k0 + tig][m + 8]);
                af[mt][2] = __float_as_uint(As[buf][k0 + tig + 4][m]);
                af[mt][3] = __float_as_uint(As[buf][k0 + tig + 4][m + 8]);
            }
            u32 bf[NT][2];
#pragma unroll
            for (int nt = 0; nt < NT; nt++) {
                int n = wn * WTN + nt * 8 + grp;
                bf[nt][0] = __float_as_uint(Ws[buf][k0 + tig][n]);
                bf[nt][1] = __float_as_uint(Ws[buf][k0 + tig + 4][n]);
            }
#pragma unroll
            for (int mt = 0; mt < MT; mt++)
#pragma unroll
                for (int nt = 0; nt < NT; nt++)
                    mma_tf32(acc[mt][nt], af[mt][0], af[mt][1], af[mt][2], af[mt][3],
                             bf[nt][0], bf[nt][1]);
        }
        if (more) {
            stsG(buf ^ 1);
            __syncthreads();
            buf ^= 1;
        }
    }

    const float bnscale = rsqrtf(1.0f + 1e-5f);
    auto emit = [&](int mrow, int n, float v0, float v1) {
        if (EPI == 3) {
            C[(size_t)mrow * ldc + n]     += v0 + bias[n];
            C[(size_t)mrow * ldc + n + 1] += v1 + bias[n + 1];
            return;
        }
        if (EPI == 0) {
            if (bias) { v0 += bias[n]; v1 += bias[n + 1]; }
        } else if (EPI == 1) {
            v0 = fmaxf((v0 + bias[n]) * (p1[n] * bnscale) + p2[n], 0.f);
            v1 = fmaxf((v1 + bias[n + 1]) * (p1[n + 1] * bnscale) + p2[n + 1], 0.f);
        } else if (EPI == 2) {
            v0 += bias[n]; v1 += bias[n + 1];
            v0 = fmaxf(v0, 0.f) + log1pf(expf(-fabsf(v0)));
            v1 = fmaxf(v1, 0.f) + log1pf(expf(-fabsf(v1)));
        }
        float2 o; o.x = v0; o.y = v1;
        *(float2*)&C[(size_t)mrow * ldc + n] = o;
    };

#pragma unroll
    for (int mt = 0; mt < MT; mt++) {
        int mrow = m0 + wm * WTM + mt * 16 + grp;
#pragma unroll
        for (int nt = 0; nt < NT; nt++) {
            int n = n0 + wn * WTN + nt * 8 + tig * 2;
            emit(mrow,     n, acc[mt][nt][0], acc[mt][nt][1]);
            emit(mrow + 8, n, acc[mt][nt][2], acc[mt][nt][3]);
        }
    }
}

// ---------------------------------------------------------------------------
// Pad xp_w (56x768 -> 64x768, zero rows) and dt_w (768x24 -> 768x32, zero cols)
// ---------------------------------------------------------------------------
__global__ void pad_weights(const float* __restrict__ xp_w,
                            const float* __restrict__ dt_w) {
    int idx = blockIdx.x * 256 + threadIdx.x;
    constexpr int NXP = cNL * 64 * cDI;
    constexpr int NDT = cNL * cDI * 32;
    if (idx < NXP) {
        int l = idx / (64 * cDI);
        int r = (idx / cDI) % 64;
        int k = idx % cDI;
        g_xpw[idx] = (r < 56) ? xp_w[((size_t)l * 56 + r) * cDI + k] : 0.f;
    } else if (idx < NXP + NDT) {
        int j = idx - NXP;
        int l = j / (cDI * 32);
        int d = (j / 32) % cDI;
        int k = j % 32;
        g_dtw[j] = (k < 24) ? dt_w[((size_t)l * cDI + d) * cDTR + k] : 0.f;
    }
}

// ---------------------------------------------------------------------------
// FPS: per batch, exact replication of reference scan (incl. tie-breaking)
// ---------------------------------------------------------------------------
__global__ void fps_kernel(const float* __restrict__ xyz) {
    int b = blockIdx.x;
    __shared__ float px[cN], py[cN], pz[cN], dmin[cN];
    __shared__ float wv[8];
    __shared__ int   wi[8];
    __shared__ int   s_cur;
    int tid = threadIdx.x;
    int wid = tid >> 5, lane = tid & 31;
    for (int i = tid; i < cN; i += 256) {
        px[i] = xyz[(b * cN + i) * 3 + 0];
        py[i] = xyz[(b * cN + i) * 3 + 1];
        pz[i] = xyz[(b * cN + i) * 3 + 2];
        dmin[i] = 1e10f;
    }
    __syncthreads();
    int cur = 0;
    for (int g = 0; g < cG; g++) {
        float cx = px[cur], cy = py[cur], cz = pz[cur];
        if (tid == 0) {
            g_center[(b * cG + g) * 3 + 0] = cx;
            g_center[(b * cG + g) * 3 + 1] = cy;
            g_center[(b * cG + g) * 3 + 2] = cz;
        }
        float bv = -1.f; int bi = 0x7fffffff;
        for (int i = tid; i < cN; i += 256) {
            float dx = __fsub_rn(px[i], cx);
            float dy = __fsub_rn(py[i], cy);
            float dz = __fsub_rn(pz[i], cz);
            float dd = __fadd_rn(__fadd_rn(__fmul_rn(dx, dx), __fmul_rn(dy, dy)),
                                 __fmul_rn(dz, dz));
            float dm = fminf(dmin[i], dd);
            dmin[i] = dm;
            if (dm > bv) { bv = dm; bi = i; }
        }
#pragma unroll
        for (int off = 16; off > 0; off >>= 1) {
            float ov = __shfl_xor_sync(0xffffffffu, bv, off);
            int oi = __shfl_xor_sync(0xffffffffu, bi, off);
            if (ov > bv || (ov == bv && oi < bi)) { bv = ov; bi = oi; }
        }
        if (lane == 0) { wv[wid] = bv; wi[wid] = bi; }
        __syncthreads();
        if (tid < 8) {
            bv = wv[tid]; bi = wi[tid];
#pragma unroll
            for (int off = 4; off > 0; off >>= 1) {
                float ov = __shfl_xor_sync(0xffu, bv, off);
                int oi = __shfl_xor_sync(0xffu, bi, off);
                if (ov > bv || (ov == bv && oi < bi)) { bv = ov; bi = oi; }
            }
            if (tid == 0) s_cur = bi;
        }
        __syncthreads();
        cur = s_cur;
    }
}

// ---------------------------------------------------------------------------
// KNN: 32 smallest d2, ties -> lowest index; writes nb
// ---------------------------------------------------------------------------
__global__ void knn_kernel(const float* __restrict__ xyz) {
    int bg = blockIdx.x;
    int b = bg >> 7;
    __shared__ float d2s[cN];
    __shared__ float wv[8];
    __shared__ int   wi[8];
    __shared__ int   s_idx;
    int tid = threadIdx.x;
    int wid = tid >> 5, lane = tid & 31;
    float cx = g_center[bg * 3 + 0], cy = g_center[bg * 3 + 1], cz = g_center[bg * 3 + 2];
    const float* P = xyz + (size_t)b * cN * 3;
    for (int i = tid; i < cN; i += 256) {
        float dx = __fsub_rn(cx, P[i * 3 + 0]);
        float dy = __fsub_rn(cy, P[i * 3 + 1]);
        float dz = __fsub_rn(cz, P[i * 3 + 2]);
        d2s[i] = __fadd_rn(__fadd_rn(__fmul_rn(dx, dx), __fmul_rn(dy, dy)),
                           __fmul_rn(dz, dz));
    }
    __syncthreads();
    for (int m = 0; m < cM; m++) {
        float bv = FLT_MAX; int bi = 0x7fffffff;
        for (int i = tid; i < cN; i += 256) {
            float v = d2s[i];
            if (v < bv) { bv = v; bi = i; }
        }
#pragma unroll
        for (int off = 16; off > 0; off >>= 1) {
            float ov = __shfl_xor_sync(0xffffffffu, bv, off);
            int oi = __shfl_xor_sync(0xffffffffu, bi, off);
            if (ov < bv || (ov == bv && oi < bi)) { bv = ov; bi = oi; }
        }
        if (lane == 0) { wv[wid] = bv; wi[wid] = bi; }
        __syncthreads();
        if (tid < 8) {
            bv = wv[tid]; bi = wi[tid];
#pragma unroll
            for (int off = 4; off > 0; off >>= 1) {
                float ov = __shfl_xor_sync(0xffu, bv, off);
                int oi = __shfl_xor_sync(0xffu, bi, off);
                if (ov < bv || (ov == bv && oi < bi)) { bv = ov; bi = oi; }
            }
            if (tid == 0) s_idx = bi;
        }
        __syncthreads();
        int idx = s_idx;
        if (tid < 3) {
            float c = (tid == 0) ? cx : ((tid == 1) ? cy : cz);
            g_nb[((size_t)bg * cM + m) * 3 + tid] = __fsub_rn(P[idx * 3 + tid], c);
        }
        if (tid == 0) d2s[idx] = FLT_MAX;
        __syncthreads();
    }
}

// ---------------------------------------------------------------------------
// Encoder stage 1: f1 = relu(bn(x @ e1w1^T + e1b1))
// ---------------------------------------------------------------------------
__global__ void f1_kernel(const float* __restrict__ w1, const float* __restrict__ b1,
                          const float* __restrict__ g1, const float* __restrict__ bb1) {
    int i = blockIdx.x;
    int j = threadIdx.x;
    float x0 = g_nb[i * 3 + 0], x1 = g_nb[i * 3 + 1], x2 = g_nb[i * 3 + 2];
    float v = x0 * w1[j * 3 + 0] + x1 * w1[j * 3 + 1] + x2 * w1[j * 3 + 2] + b1[j];
    v = v * (g1[j] * rsqrtf(1.0f + 1e-5f)) + bb1[j];
    g_f1[(size_t)i * 128 + j] = fmaxf(v, 0.f);
}

// Group max of f2 -> compact g_fg[2048][256]
__global__ void fgmax_kernel() {
    int g = blockIdx.x, c = threadIdx.x;
    float mx = -FLT_MAX;
    for (int m = 0; m < cM; m++)
        mx = fmaxf(mx, g_f2[((size_t)g * cM + m) * 256 + c]);
    g_fg[g * 256 + c] = mx;
}

// tokens = max over M of f4 -> g_h
__global__ void tokmax_kernel() {
    int bg = blockIdx.x;
    for (int j = 0; j < 3; j++) {
        int c = threadIdx.x + j * 128;
        float mx = -FLT_MAX;
        for (int m = 0; m < cM; m++)
            mx = fmaxf(mx, g_f4[((size_t)bg * cM + m) * 384 + c]);
        g_h[bg * 384 + c] = mx;
    }
}

// ---------------------------------------------------------------------------
// Positional MLP stage 1 (gelu)
// ---------------------------------------------------------------------------
__global__ void pos1_kernel(const float* __restrict__ pw1, const float* __restrict__ pb1) {
    int idx = blockIdx.x * blockDim.x + threadIdx.x;
    if (idx >= cTOK * 128) return;
    int t = idx >> 7, j = idx & 127;
    float x0 = g_center[t * 3 + 0], x1 = g_center[t * 3 + 1], x2 = g_center[t * 3 + 2];
    float v = x0 * pw1[j * 3 + 0] + x1 * pw1[j * 3 + 1] + x2 * pw1[j * 3 + 2] + pb1[j];
    float v3 = v * v * v;
    float g = 0.5f * v * (1.0f + tanhf(0.7978845608028654f * (v + 0.044715f * v3)));
    g_pos1[idx] = g;
}

// ---------------------------------------------------------------------------
// Residual accumulate + LayerNorm
// ---------------------------------------------------------------------------
__device__ __forceinline__ float block_sum_128(float v, float* sm) {
    int tid = threadIdx.x;
    sm[tid] = v; __syncthreads();
    for (int s = 64; s > 0; s >>= 1) {
        if (tid < s) sm[tid] += sm[tid + s];
        __syncthreads();
    }
    float r = sm[0]; __syncthreads();
    return r;
}

__global__ void resln_kernel(const float* __restrict__ w, const float* __restrict__ b,
                             int first) {
    __shared__ float sm[128];
    int t = blockIdx.x;
    float v[3];
#pragma unroll
    for (int j = 0; j < 3; j++) {
        int c = threadIdx.x + j * 128;
        float r = g_h[t * 384 + c];
        if (!first) r += g_res[t * 384 + c];
        g_res[t * 384 + c] = r;
        v[j] = r;
    }
    float mean = block_sum_128(v[0] + v[1] + v[2], sm) * (1.0f / 384.0f);
    float sq = 0.f;
#pragma unroll
    for (int j = 0; j < 3; j++) { float d = v[j] - mean; sq += d * d; }
    float var = block_sum_128(sq, sm) * (1.0f / 384.0f);
    float inv = rsqrtf(var + 1e-5f);
#pragma unroll
    for (int j = 0; j < 3; j++) {
        int c = threadIdx.x + j * 128;
        g_xln[t * 384 + c] = (v[j] - mean) * inv * w[c] + b[c];
    }
}

__global__ void final_kernel(const float* __restrict__ w, const float* __restrict__ b,
                             float* __restrict__ out) {
    __shared__ float sm[128];
    int t = blockIdx.x;
    float v[3];
#pragma unroll
    for (int j = 0; j < 3; j++) {
        int c = threadIdx.x + j * 128;
        v[j] = g_h[t * 384 + c] + g_res[t * 384 + c];
    }
    float mean = block_sum_128(v[0] + v[1] + v[2], sm) * (1.0f / 384.0f);
    float sq = 0.f;
#pragma unroll
    for (int j = 0; j < 3; j++) { float d = v[j] - mean; sq += d * d; }
    float var = block_sum_128(sq, sm) * (1.0f / 384.0f);
    float inv = rsqrtf(var + 1e-5f);
#pragma unroll
    for (int j = 0; j < 3; j++) {
        int c = threadIdx.x + j * 128;
        out[t * 384 + c] = (v[j] - mean) * inv * w[c] + b[c];
    }
}

// ---------------------------------------------------------------------------
// Depthwise causal conv (DC=4) + bias + silu
// ---------------------------------------------------------------------------
__global__ void conv_kernel(const float* __restrict__ cw, const float* __restrict__ cb) {
    int idx = blockIdx.x * blockDim.x + threadIdx.x;
    if (idx >= cTOK * cDI) return;
    int t = idx / cDI, d = idx % cDI;
    int l = t & 127;
    int tbase = t - l;
    float acc = cb[d];
#pragma unroll
    for (int k = 0; k < 4; k++) {
        int lk = l - 3 + k;
        if (lk >= 0)
            acc += g_xz[(size_t)(tbase + lk) * 1536 + d] * cw[d * 4 + k];
    }
    float sig = 1.0f / (1.0f + expf(-acc));
    g_xc[idx] = acc * sig;
}

// ---------------------------------------------------------------------------
// Selective scan + D skip + silu(z) gate (reads B/C from g_dbl64)
// ---------------------------------------------------------------------------
__global__ void scan_kernel(const float* __restrict__ Alog, const float* __restrict__ Dp) {
    int b = blockIdx.y;
    int lane16 = threadIdx.x & 15;
    int dl = threadIdx.x >> 4;
    int d = blockIdx.x * 16 + dl;
    float A = -expf(Alog[d * 16 + lane16]);
    float Dpd = Dp[d];
    float h = 0.f;
    for (int l = 0; l < 128; l++) {
        int t = b * 128 + l;
        float dt = g_dt[(size_t)t * cDI + d];
        float xin = g_xc[(size_t)t * cDI + d];
        float Bm = g_dbl64[t * 64 + 24 + lane16];
        float Cc = g_dbl64[t * 64 + 40 + lane16];
        h = expf(dt * A) * h + dt * xin * Bm;
        float y = h * Cc;
#pragma unroll
        for (int off = 8; off > 0; off >>= 1)
            y += __shfl_xor_sync(0xffffffffu, y, off, 16);
        if (lane16 == 0) {
            y += Dpd * xin;
            float z = g_xz[(size_t)t * 1536 + 768 + d];
            float sz = z / (1.0f + expf(-z));
            g_u[(size_t)t * cDI + d] = y * sz;
        }
    }
}

// ---------------------------------------------------------------------------
// Host-side launch sequence
// ---------------------------------------------------------------------------
extern "C" void kernel_launch(void* const* d_in, const int* in_sizes, int n_in,
                              void* d_out, int out_size) {
    const float* xyz   = (const float*)d_in[0];
    const float* e1w1  = (const float*)d_in[1];
    const float* e1b1  = (const float*)d_in[2];
    const float* bn1g  = (const float*)d_in[3];
    const float* bn1b  = (const float*)d_in[4];
    const float* e1w2  = (const float*)d_in[5];
    const float* e1b2  = (const float*)d_in[6];
    const float* e2w1  = (const float*)d_in[7];
    const float* e2b1  = (const float*)d_in[8];
    const float* bn2g  = (const float*)d_in[9];
    const float* bn2b  = (const float*)d_in[10];
    const float* e2w2  = (const float*)d_in[11];
    const float* e2b2  = (const float*)d_in[12];
    const float* pw1   = (const float*)d_in[13];
    const float* pb1   = (const float*)d_in[14];
    const float* pw2   = (const float*)d_in[15];
    const float* pb2   = (const float*)d_in[16];
    const float* in_w  = (const float*)d_in[17];
    const float* convw = (const float*)d_in[18];
    const float* convb = (const float*)d_in[19];
    const float* xp_w  = (const float*)d_in[20];
    const float* dt_w  = (const float*)d_in[21];
    const float* dt_b  = (const float*)d_in[22];
    const float* A_log = (const float*)d_in[23];
    const float* Dp    = (const float*)d_in[24];
    const float* out_w = (const float*)d_in[25];
    const float* lnw   = (const float*)d_in[26];
    const float* lnb   = (const float*)d_in[27];
    const float* fnw   = (const float*)d_in[28];
    const float* fnb   = (const float*)d_in[29];
    float* out = (float*)d_out;

    float *pf1, *pf2, *pfg, *pf3, *pf4, *pxln, *pxz, *pu, *ph, *ppos1, *pxc,
          *pdbl, *pdt, *pxpw, *pdtw;
    cudaGetSymbolAddress((void**)&pf1,  g_f1);
    cudaGetSymbolAddress((void**)&pf2,  g_f2);
    cudaGetSymbolAddress((void**)&pfg,  g_fg);
    cudaGetSymbolAddress((void**)&pf3,  g_f3);
    cudaGetSymbolAddress((void**)&pf4,  g_f4);
    cudaGetSymbolAddress((void**)&pxln, g_xln);
    cudaGetSymbolAddress((void**)&pxz,  g_xz);
    cudaGetSymbolAddress((void**)&pu,   g_u);
    cudaGetSymbolAddress((void**)&ph,   g_h);
    cudaGetSymbolAddress((void**)&ppos1, g_pos1);
    cudaGetSymbolAddress((void**)&pxc,  g_xc);
    cudaGetSymbolAddress((void**)&pdbl, g_dbl64);
    cudaGetSymbolAddress((void**)&pdt,  g_dt);
    cudaGetSymbolAddress((void**)&pxpw, g_xpw);
    cudaGetSymbolAddress((void**)&pdtw, g_dtw);

    // ---- weight prep (independent of data path) ----
    constexpr int NPAD = cNL * 64 * cDI + cNL * cDI * 32;
    pad_weights<<<(NPAD + 255) / 256, 256>>>(xp_w, dt_w);

    // ---- grouping ----
    fps_kernel<<<cB, 256>>>(xyz);
    knn_kernel<<<cTOK, 256>>>(xyz);

    // ---- encoder ----
    f1_kernel<<<cPTS, 128>>>(e1w1, e1b1, bn1g, bn1b);
    // f2: (65536,128)@(256,128)^T + bias -> g_f2
    tc2<128, 128, 2, 2, 0, 0><<<dim3(cPTS / 128, 2), 128>>>(
        pf1, e1w2, e1b2, nullptr, nullptr, pf2, 128, 128, 128, 256, nullptr);
    fgmax_kernel<<<cTOK, 256>>>();
    // f3: concat(fg, f2)(65536,512)@(512,512)^T -> bn+relu
    tc2<128, 128, 2, 2, 1, 1><<<dim3(cPTS / 128, 4), 128>>>(
        pf2, e2w1, e2b1, bn2g, bn2b, pf3, 512, 256, 512, 512, pfg);
    // f4: (65536,512)@(384,512)^T + bias
    tc2<128, 128, 2, 2, 0, 0><<<dim3(cPTS / 128, 3), 128>>>(
        pf3, e2w2, e2b2, nullptr, nullptr, pf4, 512, 512, 512, 384, nullptr);
    tokmax_kernel<<<cTOK, 128>>>();

    // ---- positional MLP ----
    pos1_kernel<<<(cTOK * 128 + 255) / 256, 256>>>(pw1, pb1);
    // pos2 accumulated into g_h: (2048,128)@(384,128)^T
    tc2<128, 128, 2, 2, 3, 0><<<dim3(cTOK / 128, 3), 128>>>(
        ppos1, pw2, pb2, nullptr, nullptr, ph, 128, 128, 128, 384, nullptr);

    // ---- mamba layers ----
    for (int i = 0; i < cNL; i++) {
        const float* in_w_i  = in_w  + (size_t)i * 2 * cDI * cDM;
        const float* cw_i    = convw + (size_t)i * cDI * 4;
        const float* cb_i    = convb + (size_t)i * cDI;
        const float* dtb_i   = dt_b  + (size_t)i * cDI;
        const float* Al_i    = A_log + (size_t)i * cDI * cDS;
        const float* Dp_i    = Dp    + (size_t)i * cDI;
        const float* ow_i    = out_w + (size_t)i * cDM * cDI;
        const float* lnw_i   = lnw   + (size_t)i * cDM;
        const float* lnb_i   = lnb   + (size_t)i * cDM;
        const float* xpw_i   = pxpw  + (size_t)i * 64 * cDI;
        const float* dtw_i   = pdtw  + (size_t)i * cDI * 32;

        resln_kernel<<<cTOK, 128>>>(lnw_i, lnb_i, i == 0 ? 1 : 0);
        // in-proj: (2048,384)@(1536,384)^T
        tc2<128, 128, 2, 2, 0, 0><<<dim3(cTOK / 128, 12), 128>>>(
            pxln, in_w_i, nullptr, nullptr, nullptr, pxz, 384, 384, 384, 1536, nullptr);
        conv_kernel<<<(cTOK * cDI + 255) / 256, 256>>>(cw_i, cb_i);
        // xp: (2048,768)@(64,768)^T -> g_dbl64
        tc2<128, 64, 4, 1, 0, 0><<<dim3(cTOK / 128, 1), 128>>>(
            pxc, xpw_i, nullptr, nullptr, nullptr, pdbl, 768, 768, 768, 64, nullptr);
        // dt: (2048,32pad)@(768,32)^T + bias -> softplus
        tc2<128, 128, 2, 2, 2, 0><<<dim3(cTOK / 128, 6), 128>>>(
            pdbl, dtw_i, dtb_i, nullptr, nullptr, pdt, 32, 64, 32, 768, nullptr);
        scan_kernel<<<dim3(cDI / 16, cB), 256>>>(Al_i, Dp_i);
        // out-proj: (2048,768)@(384,768)^T
        tc2<64, 128, 1, 2, 0, 0><<<dim3(cTOK / 64, 3), 64>>>(
            pu, ow_i, nullptr, nullptr, nullptr, ph, 768, 768, 768, 384, nullptr);
    }

    // ---- final LN ----
    final_kernel<<<cTOK, 128>>>(fnw, fnb, out);
}